// round 2
// baseline (speedup 1.0000x reference)
#include <cuda_runtime.h>
#include <cuda_bf16.h>
#include <math.h>

// ---------------- problem constants ----------------
#define N_USER   100000
#define N_ITEM   50000
#define NTOT     (N_USER + N_ITEM)     // 150000
#define EMB      64
#define FEAT     384
#define NNZ      2400000
#define N_PROMPT 8
#define N_LAYERS 4
#define EPS_     1e-8f

#define SCAN_BLK 256
#define NB_SCAN  ((NTOT + SCAN_BLK - 1) / SCAN_BLK)   // 586

// ---------------- device scratch (static, no runtime alloc) ----------------
__device__ float  g_ego [NTOT * EMB];     // layer-0 embeddings (= x0)
__device__ float  g_xA  [NTOT * EMB];     // ping
__device__ float  g_xB  [NTOT * EMB];     // pong
__device__ float  g_norm[NTOT];           // ||ego|| per row
__device__ float  g_prompt[EMB];          // sum of prompt embeddings
__device__ int    g_deg   [NTOT];
__device__ int    g_rowptr[NTOT + 1];
__device__ int    g_cursor[NTOT];
__device__ int    g_bsums [1024];
__device__ int    g_boffs [1024];
__device__ int2   g_edges [NNZ];          // {col, float-bits(val)} packed per edge

// ---------------- 1) prompt sum ----------------
__global__ void k_prompt(const float* __restrict__ pe) {
    int t = threadIdx.x;              // 64 threads
    float s = 0.f;
    #pragma unroll
    for (int p = 0; p < N_PROMPT; ++p) s += pe[p * EMB + t];
    g_prompt[t] = s;
}

// ---------------- 2) user ego = user_fea + prompt ----------------
__global__ void k_user_ego(const float* __restrict__ uf) {
    int i = blockIdx.x * blockDim.x + threadIdx.x;
    if (i < N_USER * EMB)
        g_ego[i] = uf[i] + g_prompt[i & (EMB - 1)];
}

// ---------------- 3) item GEMM + tanh -> ego ----------------
__global__ __launch_bounds__(256) void k_gemm(const float* __restrict__ A,   // [N_ITEM, FEAT]
                                              const float* __restrict__ B,   // [FEAT, EMB]
                                              const float* __restrict__ bias)
{
    __shared__ float As[64][32];   // [row][k]
    __shared__ float Bs[32][64];   // [k][col]

    const int t     = threadIdx.x;
    const int c     = t & 63;            // output column 0..63
    const int rq    = t >> 6;            // row quadrant 0..3
    const int row0  = blockIdx.x * 64;

    float acc[16];
    #pragma unroll
    for (int j = 0; j < 16; ++j) acc[j] = 0.f;

    for (int k0 = 0; k0 < FEAT; k0 += 32) {
        #pragma unroll
        for (int i = 0; i < 8; ++i) {
            int lin = i * 256 + t;
            int r = lin >> 5, k = lin & 31;
            int gr = row0 + r;
            As[r][k] = (gr < N_ITEM) ? A[gr * FEAT + k0 + k] : 0.f;
        }
        #pragma unroll
        for (int i = 0; i < 8; ++i) {
            int lin = i * 256 + t;
            int k = lin >> 6, cc = lin & 63;
            Bs[k][cc] = B[(k0 + k) * EMB + cc];
        }
        __syncthreads();

        float bv[32];
        #pragma unroll
        for (int kk = 0; kk < 32; ++kk) bv[kk] = Bs[kk][c];

        #pragma unroll
        for (int j = 0; j < 16; ++j) {
            const float4* ar = (const float4*)&As[rq * 16 + j][0];
            #pragma unroll
            for (int q = 0; q < 8; ++q) {
                float4 a = ar[q];
                acc[j] += a.x * bv[4*q] + a.y * bv[4*q+1]
                        + a.z * bv[4*q+2] + a.w * bv[4*q+3];
            }
        }
        __syncthreads();
    }

    float bb = bias[c];
    #pragma unroll
    for (int j = 0; j < 16; ++j) {
        int row = row0 + rq * 16 + j;
        if (row < N_ITEM)
            g_ego[(N_USER + row) * EMB + c] = tanhf(acc[j] + bb);
    }
}

// ---------------- 4) per-row norm only (out-init fused into first prop) ----
__global__ void k_norm() {
    int gw   = (blockIdx.x * blockDim.x + threadIdx.x) >> 5;
    int lane = threadIdx.x & 31;
    if (gw >= NTOT) return;
    const float2* e2 = (const float2*)g_ego;
    float2 v = e2[gw * 32 + lane];
    float s = v.x * v.x + v.y * v.y;
    #pragma unroll
    for (int o = 16; o; o >>= 1) s += __shfl_xor_sync(0xffffffffu, s, o);
    if (lane == 0) g_norm[gw] = sqrtf(s);
}

// ---------------- CSR build ----------------
__global__ void k_zero_deg() {
    int i = blockIdx.x * blockDim.x + threadIdx.x;
    if (i < NTOT) g_deg[i] = 0;
}
__global__ void k_hist(const int* __restrict__ rows) {
    int e = blockIdx.x * blockDim.x + threadIdx.x;
    if (e < NNZ) atomicAdd(&g_deg[rows[e]], 1);
}
__global__ void k_scan1() {
    __shared__ int sh[SCAN_BLK];
    int t = threadIdx.x;
    int idx = blockIdx.x * SCAN_BLK + t;
    int v = (idx < NTOT) ? g_deg[idx] : 0;
    sh[t] = v;
    __syncthreads();
    for (int off = 1; off < SCAN_BLK; off <<= 1) {
        int add = (t >= off) ? sh[t - off] : 0;
        __syncthreads();
        sh[t] += add;
        __syncthreads();
    }
    if (idx < NTOT) g_rowptr[idx] = sh[t] - v;      // exclusive
    if (t == SCAN_BLK - 1) g_bsums[blockIdx.x] = sh[t];
}
__global__ void k_scan2() {                          // 1 block, 1024 threads
    __shared__ int sh[1024];
    int t = threadIdx.x;
    int v = (t < NB_SCAN) ? g_bsums[t] : 0;
    sh[t] = v;
    __syncthreads();
    for (int off = 1; off < 1024; off <<= 1) {
        int add = (t >= off) ? sh[t - off] : 0;
        __syncthreads();
        sh[t] += add;
        __syncthreads();
    }
    if (t < NB_SCAN) g_boffs[t] = sh[t] - v;         // exclusive
    if (t == 1023)   g_rowptr[NTOT] = sh[1023];      // == NNZ
}
__global__ void k_scan3() {
    int i = blockIdx.x * blockDim.x + threadIdx.x;
    if (i < NTOT) {
        int r = g_rowptr[i] + g_boffs[i >> 8];
        g_rowptr[i] = r;
        g_cursor[i] = r;
    }
}
__global__ void k_scatter(const int* __restrict__ rows,
                          const int* __restrict__ cols,
                          const float* __restrict__ vals) {
    int e = blockIdx.x * blockDim.x + threadIdx.x;
    if (e < NNZ) {
        int p = atomicAdd(&g_cursor[rows[e]], 1);
        g_edges[p] = make_int2(cols[e], __float_as_int(vals[e]));
    }
}

// ---------------- fused propagate layer (warp per row) ----------------
// Edge indices/values are loaded COALESCED (32 edges per LDG.64 across the
// warp) and broadcast via shfl; gathers are issued in unrolled groups of 8
// for MLP=8 on the L2-resident x-table.
// FIRST:    out = ego + r   (no out read; fuses out-init)
// WRITE_XN: store the re-weighted x for the next layer (skipped on last)
template<bool FIRST, bool WRITE_XN>
__global__ __launch_bounds__(256) void k_prop(const float2* __restrict__ x,
                                              float2* __restrict__ xn,
                                              float2* __restrict__ out)
{
    const unsigned FULL = 0xffffffffu;
    int gw   = (blockIdx.x * blockDim.x + threadIdx.x) >> 5;
    int lane = threadIdx.x & 31;
    if (gw >= NTOT) return;

    int beg = g_rowptr[gw];
    int end = g_rowptr[gw + 1];

    float2 acc = make_float2(0.f, 0.f);

    for (int base = beg; base < end; base += 32) {
        int cnt = end - base;
        if (cnt > 32) cnt = 32;
        int2 cv = make_int2(0, 0);
        if (lane < cnt) cv = g_edges[base + lane];   // coalesced 256B edge load

        int j = 0;
        for (; j + 8 <= cnt; j += 8) {
            int c0 = __shfl_sync(FULL, cv.x, j+0);
            int c1 = __shfl_sync(FULL, cv.x, j+1);
            int c2 = __shfl_sync(FULL, cv.x, j+2);
            int c3 = __shfl_sync(FULL, cv.x, j+3);
            int c4 = __shfl_sync(FULL, cv.x, j+4);
            int c5 = __shfl_sync(FULL, cv.x, j+5);
            int c6 = __shfl_sync(FULL, cv.x, j+6);
            int c7 = __shfl_sync(FULL, cv.x, j+7);
            float v0 = __int_as_float(__shfl_sync(FULL, cv.y, j+0));
            float v1 = __int_as_float(__shfl_sync(FULL, cv.y, j+1));
            float v2 = __int_as_float(__shfl_sync(FULL, cv.y, j+2));
            float v3 = __int_as_float(__shfl_sync(FULL, cv.y, j+3));
            float v4 = __int_as_float(__shfl_sync(FULL, cv.y, j+4));
            float v5 = __int_as_float(__shfl_sync(FULL, cv.y, j+5));
            float v6 = __int_as_float(__shfl_sync(FULL, cv.y, j+6));
            float v7 = __int_as_float(__shfl_sync(FULL, cv.y, j+7));
            float2 x0 = x[c0 * 32 + lane];
            float2 x1 = x[c1 * 32 + lane];
            float2 x2 = x[c2 * 32 + lane];
            float2 x3 = x[c3 * 32 + lane];
            float2 x4 = x[c4 * 32 + lane];
            float2 x5 = x[c5 * 32 + lane];
            float2 x6 = x[c6 * 32 + lane];
            float2 x7 = x[c7 * 32 + lane];
            acc.x += v0*x0.x; acc.y += v0*x0.y;
            acc.x += v1*x1.x; acc.y += v1*x1.y;
            acc.x += v2*x2.x; acc.y += v2*x2.y;
            acc.x += v3*x3.x; acc.y += v3*x3.y;
            acc.x += v4*x4.x; acc.y += v4*x4.y;
            acc.x += v5*x5.x; acc.y += v5*x5.y;
            acc.x += v6*x6.x; acc.y += v6*x6.y;
            acc.x += v7*x7.x; acc.y += v7*x7.y;
        }
        for (; j + 4 <= cnt; j += 4) {
            int c0 = __shfl_sync(FULL, cv.x, j+0);
            int c1 = __shfl_sync(FULL, cv.x, j+1);
            int c2 = __shfl_sync(FULL, cv.x, j+2);
            int c3 = __shfl_sync(FULL, cv.x, j+3);
            float v0 = __int_as_float(__shfl_sync(FULL, cv.y, j+0));
            float v1 = __int_as_float(__shfl_sync(FULL, cv.y, j+1));
            float v2 = __int_as_float(__shfl_sync(FULL, cv.y, j+2));
            float v3 = __int_as_float(__shfl_sync(FULL, cv.y, j+3));
            float2 x0 = x[c0 * 32 + lane];
            float2 x1 = x[c1 * 32 + lane];
            float2 x2 = x[c2 * 32 + lane];
            float2 x3 = x[c3 * 32 + lane];
            acc.x += v0*x0.x; acc.y += v0*x0.y;
            acc.x += v1*x1.x; acc.y += v1*x1.y;
            acc.x += v2*x2.x; acc.y += v2*x2.y;
            acc.x += v3*x3.x; acc.y += v3*x3.y;
        }
        for (; j < cnt; ++j) {
            int   c = __shfl_sync(FULL, cv.x, j);
            float v = __int_as_float(__shfl_sync(FULL, cv.y, j));
            float2 xv = x[c * 32 + lane];
            acc.x += v*xv.x; acc.y += v*xv.y;
        }
    }

    float2 eg = ((const float2*)g_ego)[gw * 32 + lane];
    float dot = acc.x * eg.x + acc.y * eg.y;
    float nrm = acc.x * acc.x + acc.y * acc.y;
    #pragma unroll
    for (int o = 16; o; o >>= 1) {
        dot += __shfl_xor_sync(FULL, dot, o);
        nrm += __shfl_xor_sync(FULL, nrm, o);
    }
    float w = dot / fmaxf(sqrtf(nrm) * g_norm[gw], EPS_);

    float2 r = make_float2(w * acc.x, w * acc.y);
    if (WRITE_XN) xn[gw * 32 + lane] = r;
    if (FIRST) {
        out[gw * 32 + lane] = make_float2(eg.x + r.x, eg.y + r.y);
    } else {
        float2 o2 = out[gw * 32 + lane];
        o2.x += r.x; o2.y += r.y;
        out[gw * 32 + lane] = o2;
    }
}

// ---------------- launch ----------------
extern "C" void kernel_launch(void* const* d_in, const int* in_sizes, int n_in,
                              void* d_out, int out_size)
{
    const float* user_fea = (const float*)d_in[0];
    const float* item_fea = (const float*)d_in[1];
    const float* prompt   = (const float*)d_in[2];
    const float* mlp_w    = (const float*)d_in[3];
    const float* mlp_b    = (const float*)d_in[4];
    const int*   adj_rows = (const int*)  d_in[5];
    const int*   adj_cols = (const int*)  d_in[6];
    const float* adj_vals = (const float*)d_in[7];
    float* out = (float*)d_out;

    // --- embeddings ---
    k_prompt  <<<1, EMB>>>(prompt);
    k_user_ego<<<(N_USER * EMB + 255) / 256, 256>>>(user_fea);
    k_gemm    <<<(N_ITEM + 63) / 64, 256>>>(item_fea, mlp_w, mlp_b);
    k_norm    <<<(NTOT * 32 + 255) / 256, 256>>>();

    // --- CSR build ---
    k_zero_deg<<<(NTOT + 255) / 256, 256>>>();
    k_hist    <<<(NNZ + 255) / 256, 256>>>(adj_rows);
    k_scan1   <<<NB_SCAN, SCAN_BLK>>>();
    k_scan2   <<<1, 1024>>>();
    k_scan3   <<<(NTOT + 255) / 256, 256>>>();
    k_scatter <<<(NNZ + 255) / 256, 256>>>(adj_rows, adj_cols, adj_vals);

    // --- 4 propagation layers (ping-pong; layer 0 reads ego) ---
    float2* ego2 = nullptr; float2* xA2 = nullptr; float2* xB2 = nullptr;
    cudaGetSymbolAddress((void**)&ego2, g_ego);
    cudaGetSymbolAddress((void**)&xA2,  g_xA);
    cudaGetSymbolAddress((void**)&xB2,  g_xB);
    float2* out2 = (float2*)out;

    int pblocks = (NTOT * 32 + 255) / 256;
    k_prop<true,  true ><<<pblocks, 256>>>(ego2, xA2, out2);
    k_prop<false, true ><<<pblocks, 256>>>(xA2,  xB2, out2);
    k_prop<false, true ><<<pblocks, 256>>>(xB2,  xA2, out2);
    k_prop<false, false><<<pblocks, 256>>>(xA2,  xB2, out2);
}

// round 3
// speedup vs baseline: 1.1574x; 1.1574x over previous
#include <cuda_runtime.h>
#include <cuda_bf16.h>
#include <math.h>

// ---------------- problem constants ----------------
#define N_USER   100000
#define N_ITEM   50000
#define NTOT     (N_USER + N_ITEM)     // 150000
#define EMB      64
#define FEAT     384
#define NNZ      2400000
#define N_PROMPT 8
#define N_LAYERS 4
#define EPS_     1e-8f

#define SCAN_BLK 256
#define NB_SCAN  ((NTOT + SCAN_BLK - 1) / SCAN_BLK)   // 586

// ---------------- device scratch (static, no runtime alloc) ----------------
__device__ float  g_ego [NTOT * EMB];     // layer-0 embeddings (= x0)
__device__ float  g_xA  [NTOT * EMB];     // ping
__device__ float  g_xB  [NTOT * EMB];     // pong
__device__ float  g_norm[NTOT];           // ||ego|| per row
__device__ float  g_prompt[EMB];          // sum of prompt embeddings
__device__ int    g_deg   [NTOT];
__device__ int    g_rowptr[NTOT + 1];
__device__ int    g_cursor[NTOT];
__device__ int    g_bsums [1024];
__device__ int    g_boffs [1024];
__device__ int2   g_edges [NNZ];          // {col, float-bits(val)} packed per edge

// ---------------- 1) prompt sum ----------------
__global__ void k_prompt(const float* __restrict__ pe) {
    int t = threadIdx.x;              // 64 threads
    float s = 0.f;
    #pragma unroll
    for (int p = 0; p < N_PROMPT; ++p) s += pe[p * EMB + t];
    g_prompt[t] = s;
}

// ---------------- 2) user ego = user_fea + prompt ----------------
__global__ void k_user_ego(const float* __restrict__ uf) {
    int i = blockIdx.x * blockDim.x + threadIdx.x;
    if (i < N_USER * EMB)
        g_ego[i] = uf[i] + g_prompt[i & (EMB - 1)];
}

// ---------------- 3) item GEMM + tanh -> ego ----------------
__global__ __launch_bounds__(256) void k_gemm(const float* __restrict__ A,   // [N_ITEM, FEAT]
                                              const float* __restrict__ B,   // [FEAT, EMB]
                                              const float* __restrict__ bias)
{
    __shared__ float As[64][32];   // [row][k]
    __shared__ float Bs[32][64];   // [k][col]

    const int t     = threadIdx.x;
    const int c     = t & 63;            // output column 0..63
    const int rq    = t >> 6;            // row quadrant 0..3
    const int row0  = blockIdx.x * 64;

    float acc[16];
    #pragma unroll
    for (int j = 0; j < 16; ++j) acc[j] = 0.f;

    for (int k0 = 0; k0 < FEAT; k0 += 32) {
        #pragma unroll
        for (int i = 0; i < 8; ++i) {
            int lin = i * 256 + t;
            int r = lin >> 5, k = lin & 31;
            int gr = row0 + r;
            As[r][k] = (gr < N_ITEM) ? A[gr * FEAT + k0 + k] : 0.f;
        }
        #pragma unroll
        for (int i = 0; i < 8; ++i) {
            int lin = i * 256 + t;
            int k = lin >> 6, cc = lin & 63;
            Bs[k][cc] = B[(k0 + k) * EMB + cc];
        }
        __syncthreads();

        float bv[32];
        #pragma unroll
        for (int kk = 0; kk < 32; ++kk) bv[kk] = Bs[kk][c];

        #pragma unroll
        for (int j = 0; j < 16; ++j) {
            const float4* ar = (const float4*)&As[rq * 16 + j][0];
            #pragma unroll
            for (int q = 0; q < 8; ++q) {
                float4 a = ar[q];
                acc[j] += a.x * bv[4*q] + a.y * bv[4*q+1]
                        + a.z * bv[4*q+2] + a.w * bv[4*q+3];
            }
        }
        __syncthreads();
    }

    float bb = bias[c];
    #pragma unroll
    for (int j = 0; j < 16; ++j) {
        int row = row0 + rq * 16 + j;
        if (row < N_ITEM)
            g_ego[(N_USER + row) * EMB + c] = tanhf(acc[j] + bb);
    }
}

// ---------------- CSR build ----------------
__global__ void k_zero_deg() {
    int i = blockIdx.x * blockDim.x + threadIdx.x;
    if (i < NTOT) g_deg[i] = 0;
}
__global__ void k_hist(const int* __restrict__ rows) {
    int e = blockIdx.x * blockDim.x + threadIdx.x;
    if (e < NNZ) atomicAdd(&g_deg[rows[e]], 1);
}
__global__ void k_scan1() {
    __shared__ int sh[SCAN_BLK];
    int t = threadIdx.x;
    int idx = blockIdx.x * SCAN_BLK + t;
    int v = (idx < NTOT) ? g_deg[idx] : 0;
    sh[t] = v;
    __syncthreads();
    for (int off = 1; off < SCAN_BLK; off <<= 1) {
        int add = (t >= off) ? sh[t - off] : 0;
        __syncthreads();
        sh[t] += add;
        __syncthreads();
    }
    if (idx < NTOT) g_rowptr[idx] = sh[t] - v;      // exclusive
    if (t == SCAN_BLK - 1) g_bsums[blockIdx.x] = sh[t];
}
__global__ void k_scan2() {                          // 1 block, 1024 threads
    __shared__ int sh[1024];
    int t = threadIdx.x;
    int v = (t < NB_SCAN) ? g_bsums[t] : 0;
    sh[t] = v;
    __syncthreads();
    for (int off = 1; off < 1024; off <<= 1) {
        int add = (t >= off) ? sh[t - off] : 0;
        __syncthreads();
        sh[t] += add;
        __syncthreads();
    }
    if (t < NB_SCAN) g_boffs[t] = sh[t] - v;         // exclusive
    if (t == 1023)   g_rowptr[NTOT] = sh[1023];      // == NNZ
}
__global__ void k_scan3() {
    int i = blockIdx.x * blockDim.x + threadIdx.x;
    if (i < NTOT) {
        int r = g_rowptr[i] + g_boffs[i >> 8];
        g_rowptr[i] = r;
        g_cursor[i] = r;
    }
}
__global__ void k_scatter(const int* __restrict__ rows,
                          const int* __restrict__ cols,
                          const float* __restrict__ vals) {
    int e = blockIdx.x * blockDim.x + threadIdx.x;
    if (e < NNZ) {
        int p = atomicAdd(&g_cursor[rows[e]], 1);
        g_edges[p] = make_int2(cols[e], __float_as_int(vals[e]));
    }
}

// ---------------- fused propagate layer (warp per row) ----------------
// Edge loads are warp-UNIFORM (one address per warp -> HW broadcast, no shfl).
// Manual unroll x4 gives 4 independent edge->gather chains (MLP>=4).
// FIRST:    computes ||ego|| (stores g_norm) and writes out = ego + r
//           (no out read, no separate norm kernel).
// WRITE_XN: store re-weighted x for the next layer (skipped on last layer).
template<bool FIRST, bool WRITE_XN>
__global__ __launch_bounds__(256) void k_prop(const float2* __restrict__ x,
                                              float2* __restrict__ xn,
                                              float2* __restrict__ out)
{
    const unsigned FULL = 0xffffffffu;
    int gw   = (blockIdx.x * blockDim.x + threadIdx.x) >> 5;
    int lane = threadIdx.x & 31;
    if (gw >= NTOT) return;

    int beg = g_rowptr[gw];
    int end = g_rowptr[gw + 1];

    float2 acc = make_float2(0.f, 0.f);

    int e = beg;
    for (; e + 4 <= end; e += 4) {
        int2 ea = g_edges[e+0];
        int2 eb = g_edges[e+1];
        int2 ec = g_edges[e+2];
        int2 ed = g_edges[e+3];
        float2 xa = x[ea.x * 32 + lane];
        float2 xb = x[eb.x * 32 + lane];
        float2 xc = x[ec.x * 32 + lane];
        float2 xd = x[ed.x * 32 + lane];
        float va = __int_as_float(ea.y);
        float vb = __int_as_float(eb.y);
        float vc = __int_as_float(ec.y);
        float vd = __int_as_float(ed.y);
        acc.x += va * xa.x; acc.y += va * xa.y;
        acc.x += vb * xb.x; acc.y += vb * xb.y;
        acc.x += vc * xc.x; acc.y += vc * xc.y;
        acc.x += vd * xd.x; acc.y += vd * xd.y;
    }
    for (; e < end; ++e) {
        int2  cv = g_edges[e];
        float v  = __int_as_float(cv.y);
        float2 xv = x[cv.x * 32 + lane];
        acc.x += v * xv.x; acc.y += v * xv.y;
    }

    float2 eg = ((const float2*)g_ego)[gw * 32 + lane];
    float dot = acc.x * eg.x + acc.y * eg.y;
    float nrm = acc.x * acc.x + acc.y * acc.y;
    float egn = FIRST ? (eg.x * eg.x + eg.y * eg.y) : 0.f;
    #pragma unroll
    for (int o = 16; o; o >>= 1) {
        dot += __shfl_xor_sync(FULL, dot, o);
        nrm += __shfl_xor_sync(FULL, nrm, o);
        if (FIRST) egn += __shfl_xor_sync(FULL, egn, o);
    }

    float ego_norm;
    if (FIRST) {
        ego_norm = sqrtf(egn);
        if (lane == 0) g_norm[gw] = ego_norm;       // for later layers
    } else {
        ego_norm = g_norm[gw];
    }
    float w = dot / fmaxf(sqrtf(nrm) * ego_norm, EPS_);

    float2 r = make_float2(w * acc.x, w * acc.y);
    if (WRITE_XN) xn[gw * 32 + lane] = r;
    if (FIRST) {
        out[gw * 32 + lane] = make_float2(eg.x + r.x, eg.y + r.y);
    } else {
        float2 o2 = out[gw * 32 + lane];
        o2.x += r.x; o2.y += r.y;
        out[gw * 32 + lane] = o2;
    }
}

// ---------------- launch ----------------
extern "C" void kernel_launch(void* const* d_in, const int* in_sizes, int n_in,
                              void* d_out, int out_size)
{
    const float* user_fea = (const float*)d_in[0];
    const float* item_fea = (const float*)d_in[1];
    const float* prompt   = (const float*)d_in[2];
    const float* mlp_w    = (const float*)d_in[3];
    const float* mlp_b    = (const float*)d_in[4];
    const int*   adj_rows = (const int*)  d_in[5];
    const int*   adj_cols = (const int*)  d_in[6];
    const float* adj_vals = (const float*)d_in[7];
    float* out = (float*)d_out;

    // --- embeddings ---
    k_prompt  <<<1, EMB>>>(prompt);
    k_user_ego<<<(N_USER * EMB + 255) / 256, 256>>>(user_fea);
    k_gemm    <<<(N_ITEM + 63) / 64, 256>>>(item_fea, mlp_w, mlp_b);

    // --- CSR build ---
    k_zero_deg<<<(NTOT + 255) / 256, 256>>>();
    k_hist    <<<(NNZ + 255) / 256, 256>>>(adj_rows);
    k_scan1   <<<NB_SCAN, SCAN_BLK>>>();
    k_scan2   <<<1, 1024>>>();
    k_scan3   <<<(NTOT + 255) / 256, 256>>>();
    k_scatter <<<(NNZ + 255) / 256, 256>>>(adj_rows, adj_cols, adj_vals);

    // --- 4 propagation layers (ping-pong; layer 0 reads ego) ---
    float2* ego2 = nullptr; float2* xA2 = nullptr; float2* xB2 = nullptr;
    cudaGetSymbolAddress((void**)&ego2, g_ego);
    cudaGetSymbolAddress((void**)&xA2,  g_xA);
    cudaGetSymbolAddress((void**)&xB2,  g_xB);
    float2* out2 = (float2*)out;

    int pblocks = (NTOT * 32 + 255) / 256;
    k_prop<true,  true ><<<pblocks, 256>>>(ego2, xA2, out2);
    k_prop<false, true ><<<pblocks, 256>>>(xA2,  xB2, out2);
    k_prop<false, true ><<<pblocks, 256>>>(xB2,  xA2, out2);
    k_prop<false, false><<<pblocks, 256>>>(xA2,  xB2, out2);
}

// round 4
// speedup vs baseline: 1.2728x; 1.0997x over previous
#include <cuda_runtime.h>
#include <cuda_bf16.h>
#include <math.h>

// ---------------- problem constants ----------------
#define N_USER   100000
#define N_ITEM   50000
#define NTOT     (N_USER + N_ITEM)     // 150000
#define EMB      64
#define FEAT     384
#define NNZ      2400000
#define N_PROMPT 8
#define N_LAYERS 4
#define EPS_     1e-8f

#define SCAN_BLK 256
#define NB_SCAN  ((NTOT + SCAN_BLK - 1) / SCAN_BLK)   // 586

// ---------------- device scratch (static, no runtime alloc) ----------------
__device__ float  g_ego [NTOT * EMB];     // layer-0 embeddings (= x0)
__device__ float  g_xA  [NTOT * EMB];     // ping
__device__ float  g_xB  [NTOT * EMB];     // pong
__device__ float  g_norm[NTOT];           // ||ego|| per row
__device__ float  g_prompt[EMB];          // sum of prompt embeddings
__device__ int    g_deg   [NTOT];
__device__ int    g_rowptr[NTOT + 1];
__device__ int    g_cursor[NTOT];
__device__ int    g_bsums [1024];
__device__ int    g_boffs [1024];
__device__ int2   g_edges [NNZ];          // {col, float-bits(val)} packed per edge

// ---------------- 1) prompt sum ----------------
__global__ void k_prompt(const float* __restrict__ pe) {
    int t = threadIdx.x;              // 64 threads
    float s = 0.f;
    #pragma unroll
    for (int p = 0; p < N_PROMPT; ++p) s += pe[p * EMB + t];
    g_prompt[t] = s;
}

// ---------------- 2) user ego = user_fea + prompt ----------------
__global__ void k_user_ego(const float* __restrict__ uf) {
    int i = blockIdx.x * blockDim.x + threadIdx.x;
    if (i < N_USER * EMB)
        g_ego[i] = uf[i] + g_prompt[i & (EMB - 1)];
}

// ---------------- 3) item GEMM + tanh -> ego ----------------
__global__ __launch_bounds__(256) void k_gemm(const float* __restrict__ A,   // [N_ITEM, FEAT]
                                              const float* __restrict__ B,   // [FEAT, EMB]
                                              const float* __restrict__ bias)
{
    __shared__ float As[64][32];   // [row][k]
    __shared__ float Bs[32][64];   // [k][col]

    const int t     = threadIdx.x;
    const int c     = t & 63;            // output column 0..63
    const int rq    = t >> 6;            // row quadrant 0..3
    const int row0  = blockIdx.x * 64;

    float acc[16];
    #pragma unroll
    for (int j = 0; j < 16; ++j) acc[j] = 0.f;

    for (int k0 = 0; k0 < FEAT; k0 += 32) {
        #pragma unroll
        for (int i = 0; i < 8; ++i) {
            int lin = i * 256 + t;
            int r = lin >> 5, k = lin & 31;
            int gr = row0 + r;
            As[r][k] = (gr < N_ITEM) ? A[gr * FEAT + k0 + k] : 0.f;
        }
        #pragma unroll
        for (int i = 0; i < 8; ++i) {
            int lin = i * 256 + t;
            int k = lin >> 6, cc = lin & 63;
            Bs[k][cc] = B[(k0 + k) * EMB + cc];
        }
        __syncthreads();

        float bv[32];
        #pragma unroll
        for (int kk = 0; kk < 32; ++kk) bv[kk] = Bs[kk][c];

        #pragma unroll
        for (int j = 0; j < 16; ++j) {
            const float4* ar = (const float4*)&As[rq * 16 + j][0];
            #pragma unroll
            for (int q = 0; q < 8; ++q) {
                float4 a = ar[q];
                acc[j] += a.x * bv[4*q] + a.y * bv[4*q+1]
                        + a.z * bv[4*q+2] + a.w * bv[4*q+3];
            }
        }
        __syncthreads();
    }

    float bb = bias[c];
    #pragma unroll
    for (int j = 0; j < 16; ++j) {
        int row = row0 + rq * 16 + j;
        if (row < N_ITEM)
            g_ego[(N_USER + row) * EMB + c] = tanhf(acc[j] + bb);
    }
}

// ---------------- CSR build ----------------
__global__ void k_hist(const int* __restrict__ rows) {
    int e = blockIdx.x * blockDim.x + threadIdx.x;
    if (e < NNZ) atomicAdd(&g_deg[rows[e]], 1);
}
__global__ void k_scan1() {
    __shared__ int sh[SCAN_BLK];
    int t = threadIdx.x;
    int idx = blockIdx.x * SCAN_BLK + t;
    int v = (idx < NTOT) ? g_deg[idx] : 0;
    sh[t] = v;
    __syncthreads();
    for (int off = 1; off < SCAN_BLK; off <<= 1) {
        int add = (t >= off) ? sh[t - off] : 0;
        __syncthreads();
        sh[t] += add;
        __syncthreads();
    }
    if (idx < NTOT) g_rowptr[idx] = sh[t] - v;      // exclusive
    if (t == SCAN_BLK - 1) g_bsums[blockIdx.x] = sh[t];
}
__global__ void k_scan2() {                          // 1 block, 1024 threads
    __shared__ int sh[1024];
    int t = threadIdx.x;
    int v = (t < NB_SCAN) ? g_bsums[t] : 0;
    sh[t] = v;
    __syncthreads();
    for (int off = 1; off < 1024; off <<= 1) {
        int add = (t >= off) ? sh[t - off] : 0;
        __syncthreads();
        sh[t] += add;
        __syncthreads();
    }
    if (t < NB_SCAN) g_boffs[t] = sh[t] - v;         // exclusive
    if (t == 1023)   g_rowptr[NTOT] = sh[1023];      // == NNZ
}
__global__ void k_scan3() {
    int i = blockIdx.x * blockDim.x + threadIdx.x;
    if (i < NTOT) {
        int r = g_rowptr[i] + g_boffs[i >> 8];
        g_rowptr[i] = r;
        g_cursor[i] = r;
    }
}
__global__ void k_scatter(const int* __restrict__ rows,
                          const int* __restrict__ cols,
                          const float* __restrict__ vals) {
    int e = blockIdx.x * blockDim.x + threadIdx.x;
    if (e < NNZ) {
        int p = atomicAdd(&g_cursor[rows[e]], 1);
        g_edges[p] = make_int2(cols[e], __float_as_int(vals[e]));
    }
}

// ---------------- fused propagate layer (warp per row) ----------------
// Edge loads are warp-UNIFORM (one address per warp -> HW broadcast, no shfl).
// Manual unroll x8 gives 8 independent edge->gather chains (MLP>=8; mean
// degree is 16 so an average row is 2 iterations).
// FIRST:    computes ||ego|| (stores g_norm) and writes out = ego + r.
// WRITE_XN: store re-weighted x for the next layer (skipped on last layer).
template<bool FIRST, bool WRITE_XN>
__global__ __launch_bounds__(256) void k_prop(const float2* __restrict__ x,
                                              float2* __restrict__ xn,
                                              float2* __restrict__ out)
{
    const unsigned FULL = 0xffffffffu;
    int gw   = (blockIdx.x * blockDim.x + threadIdx.x) >> 5;
    int lane = threadIdx.x & 31;
    if (gw >= NTOT) return;

    int beg = g_rowptr[gw];
    int end = g_rowptr[gw + 1];

    float2 acc = make_float2(0.f, 0.f);

    int e = beg;
    for (; e + 8 <= end; e += 8) {
        int2 e0 = g_edges[e+0];
        int2 e1 = g_edges[e+1];
        int2 e2 = g_edges[e+2];
        int2 e3 = g_edges[e+3];
        int2 e4 = g_edges[e+4];
        int2 e5 = g_edges[e+5];
        int2 e6 = g_edges[e+6];
        int2 e7 = g_edges[e+7];
        float2 x0 = x[e0.x * 32 + lane];
        float2 x1 = x[e1.x * 32 + lane];
        float2 x2 = x[e2.x * 32 + lane];
        float2 x3 = x[e3.x * 32 + lane];
        float2 x4 = x[e4.x * 32 + lane];
        float2 x5 = x[e5.x * 32 + lane];
        float2 x6 = x[e6.x * 32 + lane];
        float2 x7 = x[e7.x * 32 + lane];
        float v0 = __int_as_float(e0.y);
        float v1 = __int_as_float(e1.y);
        float v2 = __int_as_float(e2.y);
        float v3 = __int_as_float(e3.y);
        float v4 = __int_as_float(e4.y);
        float v5 = __int_as_float(e5.y);
        float v6 = __int_as_float(e6.y);
        float v7 = __int_as_float(e7.y);
        acc.x += v0*x0.x; acc.y += v0*x0.y;
        acc.x += v1*x1.x; acc.y += v1*x1.y;
        acc.x += v2*x2.x; acc.y += v2*x2.y;
        acc.x += v3*x3.x; acc.y += v3*x3.y;
        acc.x += v4*x4.x; acc.y += v4*x4.y;
        acc.x += v5*x5.x; acc.y += v5*x5.y;
        acc.x += v6*x6.x; acc.y += v6*x6.y;
        acc.x += v7*x7.x; acc.y += v7*x7.y;
    }
    for (; e + 2 <= end; e += 2) {
        int2 ea = g_edges[e+0];
        int2 eb = g_edges[e+1];
        float2 xa = x[ea.x * 32 + lane];
        float2 xb = x[eb.x * 32 + lane];
        float va = __int_as_float(ea.y);
        float vb = __int_as_float(eb.y);
        acc.x += va*xa.x; acc.y += va*xa.y;
        acc.x += vb*xb.x; acc.y += vb*xb.y;
    }
    if (e < end) {
        int2  cv = g_edges[e];
        float v  = __int_as_float(cv.y);
        float2 xv = x[cv.x * 32 + lane];
        acc.x += v * xv.x; acc.y += v * xv.y;
    }

    float2 eg = ((const float2*)g_ego)[gw * 32 + lane];
    float dot = acc.x * eg.x + acc.y * eg.y;
    float nrm = acc.x * acc.x + acc.y * acc.y;
    float egn = FIRST ? (eg.x * eg.x + eg.y * eg.y) : 0.f;
    #pragma unroll
    for (int o = 16; o; o >>= 1) {
        dot += __shfl_xor_sync(FULL, dot, o);
        nrm += __shfl_xor_sync(FULL, nrm, o);
        if (FIRST) egn += __shfl_xor_sync(FULL, egn, o);
    }

    float ego_norm;
    if (FIRST) {
        ego_norm = sqrtf(egn);
        if (lane == 0) g_norm[gw] = ego_norm;       // for later layers
    } else {
        ego_norm = g_norm[gw];
    }
    float w = dot / fmaxf(sqrtf(nrm) * ego_norm, EPS_);

    float2 r = make_float2(w * acc.x, w * acc.y);
    if (WRITE_XN) xn[gw * 32 + lane] = r;
    if (FIRST) {
        out[gw * 32 + lane] = make_float2(eg.x + r.x, eg.y + r.y);
    } else {
        float2 o2 = out[gw * 32 + lane];
        o2.x += r.x; o2.y += r.y;
        out[gw * 32 + lane] = o2;
    }
}

// ---------------- launch ----------------
extern "C" void kernel_launch(void* const* d_in, const int* in_sizes, int n_in,
                              void* d_out, int out_size)
{
    const float* user_fea = (const float*)d_in[0];
    const float* item_fea = (const float*)d_in[1];
    const float* prompt   = (const float*)d_in[2];
    const float* mlp_w    = (const float*)d_in[3];
    const float* mlp_b    = (const float*)d_in[4];
    const int*   adj_rows = (const int*)  d_in[5];
    const int*   adj_cols = (const int*)  d_in[6];
    const float* adj_vals = (const float*)d_in[7];
    float* out = (float*)d_out;

    // one-time host-side resources (no device memory involved)
    static cudaStream_t s2 = nullptr;
    static cudaEvent_t  evFork = nullptr, evJoin = nullptr;
    if (s2 == nullptr) {
        cudaStreamCreateWithFlags(&s2, cudaStreamNonBlocking);
        cudaEventCreateWithFlags(&evFork, cudaEventDisableTiming);
        cudaEventCreateWithFlags(&evJoin, cudaEventDisableTiming);
    }

    void* degp = nullptr;
    float2* ego2 = nullptr; float2* xA2 = nullptr; float2* xB2 = nullptr;
    cudaGetSymbolAddress(&degp, g_deg);
    cudaGetSymbolAddress((void**)&ego2, g_ego);
    cudaGetSymbolAddress((void**)&xA2,  g_xA);
    cudaGetSymbolAddress((void**)&xB2,  g_xB);
    float2* out2 = (float2*)out;

    // ---- fork: CSR build on s2, embeddings on capture (default) stream ----
    cudaEventRecord(evFork, 0);
    cudaStreamWaitEvent(s2, evFork, 0);

    // branch A (default stream): embeddings
    k_prompt  <<<1, EMB>>>(prompt);
    k_user_ego<<<(N_USER * EMB + 255) / 256, 256>>>(user_fea);
    k_gemm    <<<(N_ITEM + 63) / 64, 256>>>(item_fea, mlp_w, mlp_b);

    // branch B (s2): CSR build
    cudaMemsetAsync(degp, 0, NTOT * sizeof(int), s2);
    k_hist    <<<(NNZ + 255) / 256, 256, 0, s2>>>(adj_rows);
    k_scan1   <<<NB_SCAN, SCAN_BLK, 0, s2>>>();
    k_scan2   <<<1, 1024, 0, s2>>>();
    k_scan3   <<<(NTOT + 255) / 256, 256, 0, s2>>>();
    k_scatter <<<(NNZ + 255) / 256, 256, 0, s2>>>(adj_rows, adj_cols, adj_vals);

    // ---- join ----
    cudaEventRecord(evJoin, s2);
    cudaStreamWaitEvent(0, evJoin, 0);

    // --- 4 propagation layers (ping-pong; layer 0 reads ego) ---
    int pblocks = (NTOT * 32 + 255) / 256;
    k_prop<true,  true ><<<pblocks, 256>>>(ego2, xA2, out2);
    k_prop<false, true ><<<pblocks, 256>>>(xA2,  xB2, out2);
    k_prop<false, true ><<<pblocks, 256>>>(xB2,  xA2, out2);
    k_prop<false, false><<<pblocks, 256>>>(xA2,  xB2, out2);
}

// round 5
// speedup vs baseline: 1.4359x; 1.1281x over previous
#include <cuda_runtime.h>
#include <cuda_bf16.h>
#include <math.h>

// ---------------- problem constants ----------------
#define N_USER   100000
#define N_ITEM   50000
#define NTOT     (N_USER + N_ITEM)     // 150000
#define EMB      64
#define FEAT     384
#define NNZ      2400000
#define N_PROMPT 8
#define N_LAYERS 4
#define EPS_     1e-8f

#define SCAN_BLK 256
#define NB_SCAN  ((NTOT + SCAN_BLK - 1) / SCAN_BLK)   // 586

// ---------------- device scratch (static, no runtime alloc) ----------------
__device__ float  g_ego [NTOT * EMB];     // layer-0 embeddings (= x0)
__device__ float  g_xA  [NTOT * EMB];     // ping
__device__ float  g_xB  [NTOT * EMB];     // pong
__device__ float  g_norm[NTOT];           // ||ego|| per row
__device__ int    g_deg   [NTOT];
__device__ int    g_rowptr[NTOT + 1];
__device__ int    g_cursor[NTOT];
__device__ int    g_bsums [1024];
__device__ int    g_boffs [1024];
__device__ int2   g_edges [NNZ];          // {col, float-bits(val)} packed per edge

// ---------------- 1) user ego = user_fea + prompt-sum (fused) ----------------
__global__ void k_user_ego(const float* __restrict__ uf,
                           const float* __restrict__ pe) {
    int i = blockIdx.x * blockDim.x + threadIdx.x;
    if (i >= N_USER * EMB) return;
    int c = i & (EMB - 1);
    float s = 0.f;
    #pragma unroll
    for (int p = 0; p < N_PROMPT; ++p) s += __ldg(&pe[p * EMB + c]);
    g_ego[i] = uf[i] + s;
}

// ---------------- 2) item GEMM + tanh -> ego ----------------
__global__ __launch_bounds__(256) void k_gemm(const float* __restrict__ A,   // [N_ITEM, FEAT]
                                              const float* __restrict__ B,   // [FEAT, EMB]
                                              const float* __restrict__ bias)
{
    __shared__ float As[64][32];   // [row][k]
    __shared__ float Bs[32][64];   // [k][col]

    const int t     = threadIdx.x;
    const int c     = t & 63;            // output column 0..63
    const int rq    = t >> 6;            // row quadrant 0..3
    const int row0  = blockIdx.x * 64;

    float acc[16];
    #pragma unroll
    for (int j = 0; j < 16; ++j) acc[j] = 0.f;

    for (int k0 = 0; k0 < FEAT; k0 += 32) {
        #pragma unroll
        for (int i = 0; i < 8; ++i) {
            int lin = i * 256 + t;
            int r = lin >> 5, k = lin & 31;
            int gr = row0 + r;
            As[r][k] = (gr < N_ITEM) ? A[gr * FEAT + k0 + k] : 0.f;
        }
        #pragma unroll
        for (int i = 0; i < 8; ++i) {
            int lin = i * 256 + t;
            int k = lin >> 6, cc = lin & 63;
            Bs[k][cc] = B[(k0 + k) * EMB + cc];
        }
        __syncthreads();

        float bv[32];
        #pragma unroll
        for (int kk = 0; kk < 32; ++kk) bv[kk] = Bs[kk][c];

        #pragma unroll
        for (int j = 0; j < 16; ++j) {
            const float4* ar = (const float4*)&As[rq * 16 + j][0];
            #pragma unroll
            for (int q = 0; q < 8; ++q) {
                float4 a = ar[q];
                acc[j] += a.x * bv[4*q] + a.y * bv[4*q+1]
                        + a.z * bv[4*q+2] + a.w * bv[4*q+3];
            }
        }
        __syncthreads();
    }

    float bb = bias[c];
    #pragma unroll
    for (int j = 0; j < 16; ++j) {
        int row = row0 + rq * 16 + j;
        if (row < N_ITEM)
            g_ego[(N_USER + row) * EMB + c] = tanhf(acc[j] + bb);
    }
}

// ---------------- CSR build ----------------
__global__ void k_hist(const int* __restrict__ rows) {
    int e = blockIdx.x * blockDim.x + threadIdx.x;
    if (e < NNZ) atomicAdd(&g_deg[rows[e]], 1);
}
__global__ void k_scan1() {
    __shared__ int sh[SCAN_BLK];
    int t = threadIdx.x;
    int idx = blockIdx.x * SCAN_BLK + t;
    int v = (idx < NTOT) ? g_deg[idx] : 0;
    sh[t] = v;
    __syncthreads();
    for (int off = 1; off < SCAN_BLK; off <<= 1) {
        int add = (t >= off) ? sh[t - off] : 0;
        __syncthreads();
        sh[t] += add;
        __syncthreads();
    }
    if (idx < NTOT) g_rowptr[idx] = sh[t] - v;      // exclusive
    if (t == SCAN_BLK - 1) g_bsums[blockIdx.x] = sh[t];
}
__global__ void k_scan2() {                          // 1 block, 1024 threads
    __shared__ int sh[1024];
    int t = threadIdx.x;
    int v = (t < NB_SCAN) ? g_bsums[t] : 0;
    sh[t] = v;
    __syncthreads();
    for (int off = 1; off < 1024; off <<= 1) {
        int add = (t >= off) ? sh[t - off] : 0;
        __syncthreads();
        sh[t] += add;
        __syncthreads();
    }
    if (t < NB_SCAN) g_boffs[t] = sh[t] - v;         // exclusive
    if (t == 1023)   g_rowptr[NTOT] = sh[1023];      // == NNZ
}
__global__ void k_scan3() {
    int i = blockIdx.x * blockDim.x + threadIdx.x;
    if (i < NTOT) {
        int r = g_rowptr[i] + g_boffs[i >> 8];
        g_rowptr[i] = r;
        g_cursor[i] = r;
    }
}
__global__ void k_scatter(const int* __restrict__ rows,
                          const int* __restrict__ cols,
                          const float* __restrict__ vals) {
    int e = blockIdx.x * blockDim.x + threadIdx.x;
    if (e < NNZ) {
        int p = atomicAdd(&g_cursor[rows[e]], 1);
        g_edges[p] = make_int2(cols[e], __float_as_int(vals[e]));
    }
}

// ---------------- fused propagate layer (2 rows per warp, float4 lanes) ----
// A row is 64 floats = 16 lanes x float4. Lanes 0-15 process row 2w,
// lanes 16-31 process row 2w+1 -> one warp instruction serves 2 edges
// (one per half), halving per-edge instruction count and doubling the
// number of independent row chains per warp. Edge loads are half-warp
// uniform (2 broadcast addrs per warp). Unroll x4 -> 8 gathers in flight.
// FIRST:    computes ||ego|| (stores g_norm) and writes out = ego + r.
// WRITE_XN: store re-weighted x for next layer (skipped on last layer).
template<bool FIRST, bool WRITE_XN>
__global__ __launch_bounds__(256) void k_prop(const float4* __restrict__ x,
                                              float4* __restrict__ xn,
                                              float4* __restrict__ out)
{
    const unsigned FULL = 0xffffffffu;
    int warp = (blockIdx.x * blockDim.x + threadIdx.x) >> 5;
    int lane = threadIdx.x & 31;
    int hl   = lane & 15;              // lane within half
    int row  = warp * 2 + (lane >> 4); // half 0 -> row 2w, half 1 -> row 2w+1
    if (row >= NTOT) return;

    int beg = g_rowptr[row];
    int end = g_rowptr[row + 1];

    float4 acc = make_float4(0.f, 0.f, 0.f, 0.f);

    int e = beg;
    for (; e + 4 <= end; e += 4) {
        int2 e0 = g_edges[e+0];
        int2 e1 = g_edges[e+1];
        int2 e2 = g_edges[e+2];
        int2 e3 = g_edges[e+3];
        float4 x0 = x[e0.x * 16 + hl];
        float4 x1 = x[e1.x * 16 + hl];
        float4 x2 = x[e2.x * 16 + hl];
        float4 x3 = x[e3.x * 16 + hl];
        float v0 = __int_as_float(e0.y);
        float v1 = __int_as_float(e1.y);
        float v2 = __int_as_float(e2.y);
        float v3 = __int_as_float(e3.y);
        acc.x += v0*x0.x; acc.y += v0*x0.y; acc.z += v0*x0.z; acc.w += v0*x0.w;
        acc.x += v1*x1.x; acc.y += v1*x1.y; acc.z += v1*x1.z; acc.w += v1*x1.w;
        acc.x += v2*x2.x; acc.y += v2*x2.y; acc.z += v2*x2.z; acc.w += v2*x2.w;
        acc.x += v3*x3.x; acc.y += v3*x3.y; acc.z += v3*x3.z; acc.w += v3*x3.w;
    }
    for (; e + 2 <= end; e += 2) {
        int2 ea = g_edges[e+0];
        int2 eb = g_edges[e+1];
        float4 xa = x[ea.x * 16 + hl];
        float4 xb = x[eb.x * 16 + hl];
        float va = __int_as_float(ea.y);
        float vb = __int_as_float(eb.y);
        acc.x += va*xa.x; acc.y += va*xa.y; acc.z += va*xa.z; acc.w += va*xa.w;
        acc.x += vb*xb.x; acc.y += vb*xb.y; acc.z += vb*xb.z; acc.w += vb*xb.w;
    }
    if (e < end) {
        int2  cv = g_edges[e];
        float v  = __int_as_float(cv.y);
        float4 xv = x[cv.x * 16 + hl];
        acc.x += v*xv.x; acc.y += v*xv.y; acc.z += v*xv.z; acc.w += v*xv.w;
    }

    float4 eg = ((const float4*)g_ego)[row * 16 + hl];
    float dot = acc.x*eg.x + acc.y*eg.y + acc.z*eg.z + acc.w*eg.w;
    float nrm = acc.x*acc.x + acc.y*acc.y + acc.z*acc.z + acc.w*acc.w;
    float egn = FIRST ? (eg.x*eg.x + eg.y*eg.y + eg.z*eg.z + eg.w*eg.w) : 0.f;
    #pragma unroll
    for (int o = 8; o; o >>= 1) {          // reduce within each 16-lane half
        dot += __shfl_xor_sync(FULL, dot, o);
        nrm += __shfl_xor_sync(FULL, nrm, o);
        if (FIRST) egn += __shfl_xor_sync(FULL, egn, o);
    }

    float ego_norm;
    if (FIRST) {
        ego_norm = sqrtf(egn);
        if (hl == 0) g_norm[row] = ego_norm;       // for later layers
    } else {
        ego_norm = g_norm[row];
    }
    float w = dot / fmaxf(sqrtf(nrm) * ego_norm, EPS_);

    float4 r = make_float4(w*acc.x, w*acc.y, w*acc.z, w*acc.w);
    if (WRITE_XN) xn[row * 16 + hl] = r;
    if (FIRST) {
        out[row * 16 + hl] = make_float4(eg.x + r.x, eg.y + r.y,
                                         eg.z + r.z, eg.w + r.w);
    } else {
        float4 o4 = out[row * 16 + hl];
        o4.x += r.x; o4.y += r.y; o4.z += r.z; o4.w += r.w;
        out[row * 16 + hl] = o4;
    }
}

// ---------------- launch ----------------
extern "C" void kernel_launch(void* const* d_in, const int* in_sizes, int n_in,
                              void* d_out, int out_size)
{
    const float* user_fea = (const float*)d_in[0];
    const float* item_fea = (const float*)d_in[1];
    const float* prompt   = (const float*)d_in[2];
    const float* mlp_w    = (const float*)d_in[3];
    const float* mlp_b    = (const float*)d_in[4];
    const int*   adj_rows = (const int*)  d_in[5];
    const int*   adj_cols = (const int*)  d_in[6];
    const float* adj_vals = (const float*)d_in[7];
    float* out = (float*)d_out;

    // one-time host-side resources (no device memory involved)
    static cudaStream_t s2 = nullptr;
    static cudaEvent_t  evFork = nullptr, evJoin = nullptr;
    if (s2 == nullptr) {
        cudaStreamCreateWithFlags(&s2, cudaStreamNonBlocking);
        cudaEventCreateWithFlags(&evFork, cudaEventDisableTiming);
        cudaEventCreateWithFlags(&evJoin, cudaEventDisableTiming);
    }

    void* degp = nullptr;
    float4* ego4 = nullptr; float4* xA4 = nullptr; float4* xB4 = nullptr;
    cudaGetSymbolAddress(&degp, g_deg);
    cudaGetSymbolAddress((void**)&ego4, g_ego);
    cudaGetSymbolAddress((void**)&xA4,  g_xA);
    cudaGetSymbolAddress((void**)&xB4,  g_xB);
    float4* out4 = (float4*)out;

    // ---- fork: CSR build on s2, embeddings on capture (default) stream ----
    cudaEventRecord(evFork, 0);
    cudaStreamWaitEvent(s2, evFork, 0);

    // branch A (default stream): embeddings
    k_user_ego<<<(N_USER * EMB + 255) / 256, 256>>>(user_fea, prompt);
    k_gemm    <<<(N_ITEM + 63) / 64, 256>>>(item_fea, mlp_w, mlp_b);

    // branch B (s2): CSR build
    cudaMemsetAsync(degp, 0, NTOT * sizeof(int), s2);
    k_hist    <<<(NNZ + 255) / 256, 256, 0, s2>>>(adj_rows);
    k_scan1   <<<NB_SCAN, SCAN_BLK, 0, s2>>>();
    k_scan2   <<<1, 1024, 0, s2>>>();
    k_scan3   <<<(NTOT + 255) / 256, 256, 0, s2>>>();
    k_scatter <<<(NNZ + 255) / 256, 256, 0, s2>>>(adj_rows, adj_cols, adj_vals);

    // ---- join ----
    cudaEventRecord(evJoin, s2);
    cudaStreamWaitEvent(0, evJoin, 0);

    // --- 4 propagation layers (ping-pong; layer 0 reads ego) ---
    int nwarp   = (NTOT + 1) / 2;                      // 2 rows per warp
    int pblocks = (nwarp * 32 + 255) / 256;
    k_prop<true,  true ><<<pblocks, 256>>>(ego4, xA4, out4);
    k_prop<false, true ><<<pblocks, 256>>>(xA4,  xB4, out4);
    k_prop<false, true ><<<pblocks, 256>>>(xB4,  xA4, out4);
    k_prop<false, false><<<pblocks, 256>>>(xA4,  xB4, out4);
}

// round 6
// speedup vs baseline: 1.5878x; 1.1058x over previous
#include <cuda_runtime.h>
#include <cuda_fp16.h>
#include <math.h>

// ---------------- problem constants ----------------
#define N_USER   100000
#define N_ITEM   50000
#define NTOT     (N_USER + N_ITEM)     // 150000
#define EMB      64
#define FEAT     384
#define NNZ      2400000
#define N_PROMPT 8
#define N_LAYERS 4
#define EPS_     1e-8f

#define SCAN_BLK 256
#define NB_SCAN  ((NTOT + SCAN_BLK - 1) / SCAN_BLK)   // 586

// ---------------- device scratch (static, no runtime alloc) ----------------
__device__ float  g_ego [NTOT * EMB];     // layer-0 embeddings (= x0), fp32
__device__ uint2  g_hA  [NTOT * 16];      // ping: row = 64 half = 16 x uint2
__device__ uint2  g_hB  [NTOT * 16];      // pong
__device__ float  g_norm[NTOT];           // ||ego|| per row
__device__ int    g_deg   [NTOT];
__device__ int    g_rowptr[NTOT + 1];
__device__ int    g_cursor[NTOT];
__device__ int    g_bsums [1024];
__device__ int    g_boffs [1024];
__device__ int2   g_edges [NNZ];          // {col, float-bits(val)} per edge

// ---------------- 1) user ego = user_fea + prompt-sum (fused) --------------
__global__ void k_user_ego(const float* __restrict__ uf,
                           const float* __restrict__ pe) {
    int i = blockIdx.x * blockDim.x + threadIdx.x;
    if (i >= N_USER * EMB) return;
    int c = i & (EMB - 1);
    float s = 0.f;
    #pragma unroll
    for (int p = 0; p < N_PROMPT; ++p) s += __ldg(&pe[p * EMB + c]);
    g_ego[i] = uf[i] + s;
}

// ---------------- 2) item GEMM + tanh -> ego ----------------
__global__ __launch_bounds__(256) void k_gemm(const float* __restrict__ A,   // [N_ITEM, FEAT]
                                              const float* __restrict__ B,   // [FEAT, EMB]
                                              const float* __restrict__ bias)
{
    __shared__ float As[64][32];   // [row][k]
    __shared__ float Bs[32][64];   // [k][col]

    const int t     = threadIdx.x;
    const int c     = t & 63;
    const int rq    = t >> 6;
    const int row0  = blockIdx.x * 64;

    float acc[16];
    #pragma unroll
    for (int j = 0; j < 16; ++j) acc[j] = 0.f;

    for (int k0 = 0; k0 < FEAT; k0 += 32) {
        #pragma unroll
        for (int i = 0; i < 8; ++i) {
            int lin = i * 256 + t;
            int r = lin >> 5, k = lin & 31;
            int gr = row0 + r;
            As[r][k] = (gr < N_ITEM) ? A[gr * FEAT + k0 + k] : 0.f;
        }
        #pragma unroll
        for (int i = 0; i < 8; ++i) {
            int lin = i * 256 + t;
            int k = lin >> 6, cc = lin & 63;
            Bs[k][cc] = B[(k0 + k) * EMB + cc];
        }
        __syncthreads();

        float bv[32];
        #pragma unroll
        for (int kk = 0; kk < 32; ++kk) bv[kk] = Bs[kk][c];

        #pragma unroll
        for (int j = 0; j < 16; ++j) {
            const float4* ar = (const float4*)&As[rq * 16 + j][0];
            #pragma unroll
            for (int q = 0; q < 8; ++q) {
                float4 a = ar[q];
                acc[j] += a.x * bv[4*q] + a.y * bv[4*q+1]
                        + a.z * bv[4*q+2] + a.w * bv[4*q+3];
            }
        }
        __syncthreads();
    }

    float bb = bias[c];
    #pragma unroll
    for (int j = 0; j < 16; ++j) {
        int row = row0 + rq * 16 + j;
        if (row < N_ITEM)
            g_ego[(N_USER + row) * EMB + c] = tanhf(acc[j] + bb);
    }
}

// ---------------- CSR build ----------------
__global__ void k_hist(const int* __restrict__ rows) {
    int e = blockIdx.x * blockDim.x + threadIdx.x;
    if (e < NNZ) atomicAdd(&g_deg[rows[e]], 1);
}
__global__ void k_scan1() {
    __shared__ int sh[SCAN_BLK];
    int t = threadIdx.x;
    int idx = blockIdx.x * SCAN_BLK + t;
    int v = (idx < NTOT) ? g_deg[idx] : 0;
    sh[t] = v;
    __syncthreads();
    for (int off = 1; off < SCAN_BLK; off <<= 1) {
        int add = (t >= off) ? sh[t - off] : 0;
        __syncthreads();
        sh[t] += add;
        __syncthreads();
    }
    if (idx < NTOT) g_rowptr[idx] = sh[t] - v;
    if (t == SCAN_BLK - 1) g_bsums[blockIdx.x] = sh[t];
}
__global__ void k_scan2() {
    __shared__ int sh[1024];
    int t = threadIdx.x;
    int v = (t < NB_SCAN) ? g_bsums[t] : 0;
    sh[t] = v;
    __syncthreads();
    for (int off = 1; off < 1024; off <<= 1) {
        int add = (t >= off) ? sh[t - off] : 0;
        __syncthreads();
        sh[t] += add;
        __syncthreads();
    }
    if (t < NB_SCAN) g_boffs[t] = sh[t] - v;
    if (t == 1023)   g_rowptr[NTOT] = sh[1023];
}
__global__ void k_scan3() {
    int i = blockIdx.x * blockDim.x + threadIdx.x;
    if (i < NTOT) {
        int r = g_rowptr[i] + g_boffs[i >> 8];
        g_rowptr[i] = r;
        g_cursor[i] = r;
    }
}
__global__ void k_scatter(const int* __restrict__ rows,
                          const int* __restrict__ cols,
                          const float* __restrict__ vals) {
    int e = blockIdx.x * blockDim.x + threadIdx.x;
    if (e < NNZ) {
        int p = atomicAdd(&g_cursor[rows[e]], 1);
        g_edges[p] = make_int2(cols[e], __float_as_int(vals[e]));
    }
}

// ---------------- helpers: half row <-> float4 ----------------
__device__ __forceinline__ float4 h8_to_f4(uint2 raw) {
    __half2 h0 = *(__half2*)&raw.x;
    __half2 h1 = *(__half2*)&raw.y;
    float2 f0 = __half22float2(h0);
    float2 f1 = __half22float2(h1);
    return make_float4(f0.x, f0.y, f1.x, f1.y);
}
__device__ __forceinline__ uint2 f4_to_h8(float4 v) {
    __half2 a = __floats2half2_rn(v.x, v.y);
    __half2 b = __floats2half2_rn(v.z, v.w);
    uint2 r;
    r.x = *(unsigned*)&a;
    r.y = *(unsigned*)&b;
    return r;
}

// ---------------- fused propagate layer (2 rows per warp) ----------------
// FIRST:  gathers from fp32 g_ego (float4 lanes), computes ||ego||,
//         writes out = ego + r, writes xn as half.
// !FIRST: gathers from half table (uint2 lanes = 4 halfs), out += r.
// WRITE_XN: store re-weighted x (half) for next layer.
template<bool FIRST, bool WRITE_XN>
__global__ __launch_bounds__(256) void k_prop(const uint2* __restrict__ xh,
                                              uint2* __restrict__ xn,
                                              float4* __restrict__ out)
{
    const unsigned FULL = 0xffffffffu;
    int warp = (blockIdx.x * blockDim.x + threadIdx.x) >> 5;
    int lane = threadIdx.x & 31;
    int hl   = lane & 15;
    int row  = warp * 2 + (lane >> 4);
    if (row >= NTOT) return;

    int beg = g_rowptr[row];
    int end = g_rowptr[row + 1];

    float4 acc = make_float4(0.f, 0.f, 0.f, 0.f);
    const float4* xf = (const float4*)g_ego;        // used when FIRST

    int e = beg;
    for (; e + 4 <= end; e += 4) {
        int2 e0 = g_edges[e+0];
        int2 e1 = g_edges[e+1];
        int2 e2 = g_edges[e+2];
        int2 e3 = g_edges[e+3];
        float4 x0, x1, x2, x3;
        if (FIRST) {
            x0 = xf[e0.x * 16 + hl];
            x1 = xf[e1.x * 16 + hl];
            x2 = xf[e2.x * 16 + hl];
            x3 = xf[e3.x * 16 + hl];
        } else {
            uint2 r0 = xh[e0.x * 16 + hl];
            uint2 r1 = xh[e1.x * 16 + hl];
            uint2 r2 = xh[e2.x * 16 + hl];
            uint2 r3 = xh[e3.x * 16 + hl];
            x0 = h8_to_f4(r0);
            x1 = h8_to_f4(r1);
            x2 = h8_to_f4(r2);
            x3 = h8_to_f4(r3);
        }
        float v0 = __int_as_float(e0.y);
        float v1 = __int_as_float(e1.y);
        float v2 = __int_as_float(e2.y);
        float v3 = __int_as_float(e3.y);
        acc.x += v0*x0.x; acc.y += v0*x0.y; acc.z += v0*x0.z; acc.w += v0*x0.w;
        acc.x += v1*x1.x; acc.y += v1*x1.y; acc.z += v1*x1.z; acc.w += v1*x1.w;
        acc.x += v2*x2.x; acc.y += v2*x2.y; acc.z += v2*x2.z; acc.w += v2*x2.w;
        acc.x += v3*x3.x; acc.y += v3*x3.y; acc.z += v3*x3.z; acc.w += v3*x3.w;
    }
    for (; e < end; ++e) {
        int2  cv = g_edges[e];
        float v  = __int_as_float(cv.y);
        float4 xv;
        if (FIRST) xv = xf[cv.x * 16 + hl];
        else       xv = h8_to_f4(xh[cv.x * 16 + hl]);
        acc.x += v*xv.x; acc.y += v*xv.y; acc.z += v*xv.z; acc.w += v*xv.w;
    }

    float4 eg = ((const float4*)g_ego)[row * 16 + hl];
    float dot = acc.x*eg.x + acc.y*eg.y + acc.z*eg.z + acc.w*eg.w;
    float nrm = acc.x*acc.x + acc.y*acc.y + acc.z*acc.z + acc.w*acc.w;
    float egn = FIRST ? (eg.x*eg.x + eg.y*eg.y + eg.z*eg.z + eg.w*eg.w) : 0.f;
    #pragma unroll
    for (int o = 8; o; o >>= 1) {
        dot += __shfl_xor_sync(FULL, dot, o);
        nrm += __shfl_xor_sync(FULL, nrm, o);
        if (FIRST) egn += __shfl_xor_sync(FULL, egn, o);
    }

    float ego_norm;
    if (FIRST) {
        ego_norm = sqrtf(egn);
        if (hl == 0) g_norm[row] = ego_norm;
    } else {
        ego_norm = g_norm[row];
    }
    float w = dot / fmaxf(sqrtf(nrm) * ego_norm, EPS_);

    float4 r = make_float4(w*acc.x, w*acc.y, w*acc.z, w*acc.w);
    if (WRITE_XN) xn[row * 16 + hl] = f4_to_h8(r);
    if (FIRST) {
        out[row * 16 + hl] = make_float4(eg.x + r.x, eg.y + r.y,
                                         eg.z + r.z, eg.w + r.w);
    } else {
        float4 o4 = out[row * 16 + hl];
        o4.x += r.x; o4.y += r.y; o4.z += r.z; o4.w += r.w;
        out[row * 16 + hl] = o4;
    }
}

// ---------------- launch ----------------
extern "C" void kernel_launch(void* const* d_in, const int* in_sizes, int n_in,
                              void* d_out, int out_size)
{
    const float* user_fea = (const float*)d_in[0];
    const float* item_fea = (const float*)d_in[1];
    const float* prompt   = (const float*)d_in[2];
    const float* mlp_w    = (const float*)d_in[3];
    const float* mlp_b    = (const float*)d_in[4];
    const int*   adj_rows = (const int*)  d_in[5];
    const int*   adj_cols = (const int*)  d_in[6];
    const float* adj_vals = (const float*)d_in[7];
    float* out = (float*)d_out;

    // one-time host-side resources (no device memory involved)
    static cudaStream_t s2 = nullptr;
    static cudaEvent_t  evFork = nullptr, evJoin = nullptr;
    if (s2 == nullptr) {
        cudaStreamCreateWithFlags(&s2, cudaStreamNonBlocking);
        cudaEventCreateWithFlags(&evFork, cudaEventDisableTiming);
        cudaEventCreateWithFlags(&evJoin, cudaEventDisableTiming);
    }

    void* degp = nullptr;
    uint2* hA = nullptr; uint2* hB = nullptr;
    cudaGetSymbolAddress(&degp, g_deg);
    cudaGetSymbolAddress((void**)&hA, g_hA);
    cudaGetSymbolAddress((void**)&hB, g_hB);
    float4* out4 = (float4*)out;

    // ---- fork: CSR build on s2, embeddings on capture (default) stream ----
    cudaEventRecord(evFork, 0);
    cudaStreamWaitEvent(s2, evFork, 0);

    // branch A (default stream): embeddings
    k_user_ego<<<(N_USER * EMB + 255) / 256, 256>>>(user_fea, prompt);
    k_gemm    <<<(N_ITEM + 63) / 64, 256>>>(item_fea, mlp_w, mlp_b);

    // branch B (s2): CSR build
    cudaMemsetAsync(degp, 0, NTOT * sizeof(int), s2);
    k_hist    <<<(NNZ + 255) / 256, 256, 0, s2>>>(adj_rows);
    k_scan1   <<<NB_SCAN, SCAN_BLK, 0, s2>>>();
    k_scan2   <<<1, 1024, 0, s2>>>();
    k_scan3   <<<(NTOT + 255) / 256, 256, 0, s2>>>();
    k_scatter <<<(NNZ + 255) / 256, 256, 0, s2>>>(adj_rows, adj_cols, adj_vals);

    // ---- join ----
    cudaEventRecord(evJoin, s2);
    cudaStreamWaitEvent(0, evJoin, 0);

    // --- 4 propagation layers (layer 0 reads fp32 ego; 1-3 read half) ---
    int nwarp   = (NTOT + 1) / 2;
    int pblocks = (nwarp * 32 + 255) / 256;
    k_prop<true,  true ><<<pblocks, 256>>>(hA, hA, out4);  // ego -> hA
    k_prop<false, true ><<<pblocks, 256>>>(hA, hB, out4);  // hA  -> hB
    k_prop<false, true ><<<pblocks, 256>>>(hB, hA, out4);  // hB  -> hA
    k_prop<false, false><<<pblocks, 256>>>(hA, hB, out4);  // hA  -> (none)
}

// round 7
// speedup vs baseline: 1.6808x; 1.0586x over previous
#include <cuda_runtime.h>
#include <cuda_fp16.h>
#include <math.h>

// ---------------- problem constants ----------------
#define N_USER   100000
#define N_ITEM   50000
#define NTOT     (N_USER + N_ITEM)     // 150000
#define EMB      64
#define FEAT     384
#define NNZ      2400000
#define N_PROMPT 8
#define N_LAYERS 4
#define EPS_     1e-8f

#define SCAN_BLK 256
#define NB_SCAN  ((NTOT + SCAN_BLK - 1) / SCAN_BLK)   // 586

// ---------------- device scratch (static, no runtime alloc) ----------------
__device__ float  g_ego [NTOT * EMB];     // layer-0 embeddings, fp32
__device__ __half g_hEgo[NTOT * EMB];     // half copy of ego (gather table L0)
__device__ uint2  g_h1  [NTOT * 16];      // x1 (half rows: 16 x uint2)
__device__ uint2  g_h2  [NTOT * 16];      // x2
__device__ uint2  g_h3  [NTOT * 16];      // x3
__device__ uint2  g_h4  [NTOT * 16];      // x4
__device__ float  g_norm[NTOT];           // ||ego|| per row
__device__ int    g_deg   [NTOT];
__device__ int    g_rowptr[NTOT + 1];
__device__ int    g_cursor[NTOT];
__device__ int    g_bsums [1024];
__device__ int    g_boffs [1024];
__device__ int2   g_edges [NNZ];          // {col, float-bits(val)} per edge

// ---------------- 1) user ego = user_fea + prompt-sum (fused) --------------
__global__ void k_user_ego(const float* __restrict__ uf,
                           const float* __restrict__ pe) {
    int i = blockIdx.x * blockDim.x + threadIdx.x;
    if (i >= N_USER * EMB) return;
    int c = i & (EMB - 1);
    float s = 0.f;
    #pragma unroll
    for (int p = 0; p < N_PROMPT; ++p) s += __ldg(&pe[p * EMB + c]);
    float v = uf[i] + s;
    g_ego[i]  = v;
    g_hEgo[i] = __float2half(v);
}

// ---------------- 2) item GEMM + tanh -> ego (fp32 + half copy) ------------
__global__ __launch_bounds__(256) void k_gemm(const float* __restrict__ A,   // [N_ITEM, FEAT]
                                              const float* __restrict__ B,   // [FEAT, EMB]
                                              const float* __restrict__ bias)
{
    __shared__ float As[64][32];
    __shared__ float Bs[32][64];

    const int t     = threadIdx.x;
    const int c     = t & 63;
    const int rq    = t >> 6;
    const int row0  = blockIdx.x * 64;

    float acc[16];
    #pragma unroll
    for (int j = 0; j < 16; ++j) acc[j] = 0.f;

    for (int k0 = 0; k0 < FEAT; k0 += 32) {
        #pragma unroll
        for (int i = 0; i < 8; ++i) {
            int lin = i * 256 + t;
            int r = lin >> 5, k = lin & 31;
            int gr = row0 + r;
            As[r][k] = (gr < N_ITEM) ? A[gr * FEAT + k0 + k] : 0.f;
        }
        #pragma unroll
        for (int i = 0; i < 8; ++i) {
            int lin = i * 256 + t;
            int k = lin >> 6, cc = lin & 63;
            Bs[k][cc] = B[(k0 + k) * EMB + cc];
        }
        __syncthreads();

        float bv[32];
        #pragma unroll
        for (int kk = 0; kk < 32; ++kk) bv[kk] = Bs[kk][c];

        #pragma unroll
        for (int j = 0; j < 16; ++j) {
            const float4* ar = (const float4*)&As[rq * 16 + j][0];
            #pragma unroll
            for (int q = 0; q < 8; ++q) {
                float4 a = ar[q];
                acc[j] += a.x * bv[4*q] + a.y * bv[4*q+1]
                        + a.z * bv[4*q+2] + a.w * bv[4*q+3];
            }
        }
        __syncthreads();
    }

    float bb = bias[c];
    #pragma unroll
    for (int j = 0; j < 16; ++j) {
        int row = row0 + rq * 16 + j;
        if (row < N_ITEM) {
            float v = tanhf(acc[j] + bb);
            g_ego [(N_USER + row) * EMB + c] = v;
            g_hEgo[(N_USER + row) * EMB + c] = __float2half(v);
        }
    }
}

// ---------------- CSR build ----------------
__global__ void k_hist(const int* __restrict__ rows) {
    int e = blockIdx.x * blockDim.x + threadIdx.x;
    if (e < NNZ) atomicAdd(&g_deg[rows[e]], 1);
}
__global__ void k_scan1() {
    __shared__ int sh[SCAN_BLK];
    int t = threadIdx.x;
    int idx = blockIdx.x * SCAN_BLK + t;
    int v = (idx < NTOT) ? g_deg[idx] : 0;
    sh[t] = v;
    __syncthreads();
    for (int off = 1; off < SCAN_BLK; off <<= 1) {
        int add = (t >= off) ? sh[t - off] : 0;
        __syncthreads();
        sh[t] += add;
        __syncthreads();
    }
    if (idx < NTOT) g_rowptr[idx] = sh[t] - v;
    if (t == SCAN_BLK - 1) g_bsums[blockIdx.x] = sh[t];
}
__global__ void k_scan2() {
    __shared__ int sh[1024];
    int t = threadIdx.x;
    int v = (t < NB_SCAN) ? g_bsums[t] : 0;
    sh[t] = v;
    __syncthreads();
    for (int off = 1; off < 1024; off <<= 1) {
        int add = (t >= off) ? sh[t - off] : 0;
        __syncthreads();
        sh[t] += add;
        __syncthreads();
    }
    if (t < NB_SCAN) g_boffs[t] = sh[t] - v;
    if (t == 1023)   g_rowptr[NTOT] = sh[1023];
}
__global__ void k_scan3() {
    int i = blockIdx.x * blockDim.x + threadIdx.x;
    if (i < NTOT) {
        int r = g_rowptr[i] + g_boffs[i >> 8];
        g_rowptr[i] = r;
        g_cursor[i] = r;
    }
}
__global__ void k_scatter(const int* __restrict__ rows,
                          const int* __restrict__ cols,
                          const float* __restrict__ vals) {
    int e = blockIdx.x * blockDim.x + threadIdx.x;
    if (e < NNZ) {
        int p = atomicAdd(&g_cursor[rows[e]], 1);
        g_edges[p] = make_int2(cols[e], __float_as_int(vals[e]));
    }
}

// ---------------- helpers ----------------
__device__ __forceinline__ float4 h8_to_f4(uint2 raw) {
    __half2 h0 = *(__half2*)&raw.x;
    __half2 h1 = *(__half2*)&raw.y;
    float2 f0 = __half22float2(h0);
    float2 f1 = __half22float2(h1);
    return make_float4(f0.x, f0.y, f1.x, f1.y);
}
__device__ __forceinline__ uint2 f4_to_h8(float4 v) {
    __half2 a = __floats2half2_rn(v.x, v.y);
    __half2 b = __floats2half2_rn(v.z, v.w);
    uint2 r;
    r.x = *(unsigned*)&a;
    r.y = *(unsigned*)&b;
    return r;
}

// ---------------- fused propagate layer (2 rows per warp, half gathers) ----
// All layers gather from a half table (8B/lane), fp32 accumulate, write half
// xn. FIRST additionally computes ||ego|| -> g_norm. No out traffic here.
template<bool FIRST>
__global__ __launch_bounds__(256) void k_prop(const uint2* __restrict__ xh,
                                              uint2* __restrict__ xn)
{
    const unsigned FULL = 0xffffffffu;
    int warp = (blockIdx.x * blockDim.x + threadIdx.x) >> 5;
    int lane = threadIdx.x & 31;
    int hl   = lane & 15;
    int row  = warp * 2 + (lane >> 4);
    if (row >= NTOT) return;

    int beg = g_rowptr[row];
    int end = g_rowptr[row + 1];

    float4 acc = make_float4(0.f, 0.f, 0.f, 0.f);

    int e = beg;
    for (; e + 8 <= end; e += 8) {
        int2 e0 = g_edges[e+0];
        int2 e1 = g_edges[e+1];
        int2 e2 = g_edges[e+2];
        int2 e3 = g_edges[e+3];
        int2 e4 = g_edges[e+4];
        int2 e5 = g_edges[e+5];
        int2 e6 = g_edges[e+6];
        int2 e7 = g_edges[e+7];
        uint2 r0 = xh[e0.x * 16 + hl];
        uint2 r1 = xh[e1.x * 16 + hl];
        uint2 r2 = xh[e2.x * 16 + hl];
        uint2 r3 = xh[e3.x * 16 + hl];
        uint2 r4 = xh[e4.x * 16 + hl];
        uint2 r5 = xh[e5.x * 16 + hl];
        uint2 r6 = xh[e6.x * 16 + hl];
        uint2 r7 = xh[e7.x * 16 + hl];
        float4 x0 = h8_to_f4(r0);
        float4 x1 = h8_to_f4(r1);
        float4 x2 = h8_to_f4(r2);
        float4 x3 = h8_to_f4(r3);
        float4 x4 = h8_to_f4(r4);
        float4 x5 = h8_to_f4(r5);
        float4 x6 = h8_to_f4(r6);
        float4 x7 = h8_to_f4(r7);
        float v0 = __int_as_float(e0.y);
        float v1 = __int_as_float(e1.y);
        float v2 = __int_as_float(e2.y);
        float v3 = __int_as_float(e3.y);
        float v4 = __int_as_float(e4.y);
        float v5 = __int_as_float(e5.y);
        float v6 = __int_as_float(e6.y);
        float v7 = __int_as_float(e7.y);
        acc.x += v0*x0.x; acc.y += v0*x0.y; acc.z += v0*x0.z; acc.w += v0*x0.w;
        acc.x += v1*x1.x; acc.y += v1*x1.y; acc.z += v1*x1.z; acc.w += v1*x1.w;
        acc.x += v2*x2.x; acc.y += v2*x2.y; acc.z += v2*x2.z; acc.w += v2*x2.w;
        acc.x += v3*x3.x; acc.y += v3*x3.y; acc.z += v3*x3.z; acc.w += v3*x3.w;
        acc.x += v4*x4.x; acc.y += v4*x4.y; acc.z += v4*x4.z; acc.w += v4*x4.w;
        acc.x += v5*x5.x; acc.y += v5*x5.y; acc.z += v5*x5.z; acc.w += v5*x5.w;
        acc.x += v6*x6.x; acc.y += v6*x6.y; acc.z += v6*x6.z; acc.w += v6*x6.w;
        acc.x += v7*x7.x; acc.y += v7*x7.y; acc.z += v7*x7.z; acc.w += v7*x7.w;
    }
    for (; e + 2 <= end; e += 2) {
        int2 ea = g_edges[e+0];
        int2 eb = g_edges[e+1];
        float4 xa = h8_to_f4(xh[ea.x * 16 + hl]);
        float4 xb = h8_to_f4(xh[eb.x * 16 + hl]);
        float va = __int_as_float(ea.y);
        float vb = __int_as_float(eb.y);
        acc.x += va*xa.x; acc.y += va*xa.y; acc.z += va*xa.z; acc.w += va*xa.w;
        acc.x += vb*xb.x; acc.y += vb*xb.y; acc.z += vb*xb.z; acc.w += vb*xb.w;
    }
    if (e < end) {
        int2  cv = g_edges[e];
        float v  = __int_as_float(cv.y);
        float4 xv = h8_to_f4(xh[cv.x * 16 + hl]);
        acc.x += v*xv.x; acc.y += v*xv.y; acc.z += v*xv.z; acc.w += v*xv.w;
    }

    float4 eg = ((const float4*)g_ego)[row * 16 + hl];
    float dot = acc.x*eg.x + acc.y*eg.y + acc.z*eg.z + acc.w*eg.w;
    float nrm = acc.x*acc.x + acc.y*acc.y + acc.z*acc.z + acc.w*acc.w;
    float egn = FIRST ? (eg.x*eg.x + eg.y*eg.y + eg.z*eg.z + eg.w*eg.w) : 0.f;
    #pragma unroll
    for (int o = 8; o; o >>= 1) {
        dot += __shfl_xor_sync(FULL, dot, o);
        nrm += __shfl_xor_sync(FULL, nrm, o);
        if (FIRST) egn += __shfl_xor_sync(FULL, egn, o);
    }

    float ego_norm;
    if (FIRST) {
        ego_norm = sqrtf(egn);
        if (hl == 0) g_norm[row] = ego_norm;
    } else {
        ego_norm = g_norm[row];
    }
    float w = dot / fmaxf(sqrtf(nrm) * ego_norm, EPS_);

    float4 r = make_float4(w*acc.x, w*acc.y, w*acc.z, w*acc.w);
    xn[row * 16 + hl] = f4_to_h8(r);
}

// ---------------- epilogue: out = ego + x1 + x2 + x3 + x4 ----------------
__global__ void k_epilogue(float4* __restrict__ out) {
    int i = blockIdx.x * blockDim.x + threadIdx.x;   // lane over NTOT*16
    if (i >= NTOT * 16) return;
    float4 s = ((const float4*)g_ego)[i];
    float4 a = h8_to_f4(g_h1[i]);
    float4 b = h8_to_f4(g_h2[i]);
    float4 c = h8_to_f4(g_h3[i]);
    float4 d = h8_to_f4(g_h4[i]);
    s.x += a.x + b.x + c.x + d.x;
    s.y += a.y + b.y + c.y + d.y;
    s.z += a.z + b.z + c.z + d.z;
    s.w += a.w + b.w + c.w + d.w;
    out[i] = s;
}

// ---------------- launch ----------------
extern "C" void kernel_launch(void* const* d_in, const int* in_sizes, int n_in,
                              void* d_out, int out_size)
{
    const float* user_fea = (const float*)d_in[0];
    const float* item_fea = (const float*)d_in[1];
    const float* prompt   = (const float*)d_in[2];
    const float* mlp_w    = (const float*)d_in[3];
    const float* mlp_b    = (const float*)d_in[4];
    const int*   adj_rows = (const int*)  d_in[5];
    const int*   adj_cols = (const int*)  d_in[6];
    const float* adj_vals = (const float*)d_in[7];
    float* out = (float*)d_out;

    static cudaStream_t s2 = nullptr;
    static cudaEvent_t  evFork = nullptr, evJoin = nullptr;
    if (s2 == nullptr) {
        cudaStreamCreateWithFlags(&s2, cudaStreamNonBlocking);
        cudaEventCreateWithFlags(&evFork, cudaEventDisableTiming);
        cudaEventCreateWithFlags(&evJoin, cudaEventDisableTiming);
    }

    void* degp = nullptr;
    uint2 *hEgo = nullptr, *h1 = nullptr, *h2 = nullptr, *h3 = nullptr, *h4 = nullptr;
    cudaGetSymbolAddress(&degp, g_deg);
    cudaGetSymbolAddress((void**)&hEgo, g_hEgo);
    cudaGetSymbolAddress((void**)&h1, g_h1);
    cudaGetSymbolAddress((void**)&h2, g_h2);
    cudaGetSymbolAddress((void**)&h3, g_h3);
    cudaGetSymbolAddress((void**)&h4, g_h4);
    float4* out4 = (float4*)out;

    // ---- fork: CSR build on s2, embeddings on capture (default) stream ----
    cudaEventRecord(evFork, 0);
    cudaStreamWaitEvent(s2, evFork, 0);

    // branch A (default stream): embeddings
    k_user_ego<<<(N_USER * EMB + 255) / 256, 256>>>(user_fea, prompt);
    k_gemm    <<<(N_ITEM + 63) / 64, 256>>>(item_fea, mlp_w, mlp_b);

    // branch B (s2): CSR build
    cudaMemsetAsync(degp, 0, NTOT * sizeof(int), s2);
    k_hist    <<<(NNZ + 255) / 256, 256, 0, s2>>>(adj_rows);
    k_scan1   <<<NB_SCAN, SCAN_BLK, 0, s2>>>();
    k_scan2   <<<1, 1024, 0, s2>>>();
    k_scan3   <<<(NTOT + 255) / 256, 256, 0, s2>>>();
    k_scatter <<<(NNZ + 255) / 256, 256, 0, s2>>>(adj_rows, adj_cols, adj_vals);

    // ---- join ----
    cudaEventRecord(evJoin, s2);
    cudaStreamWaitEvent(0, evJoin, 0);

    // --- 4 propagation layers (all gathers half) + epilogue ---
    int nwarp   = (NTOT + 1) / 2;
    int pblocks = (nwarp * 32 + 255) / 256;
    k_prop<true ><<<pblocks, 256>>>(hEgo, h1);
    k_prop<false><<<pblocks, 256>>>(h1,   h2);
    k_prop<false><<<pblocks, 256>>>(h2,   h3);
    k_prop<false><<<pblocks, 256>>>(h3,   h4);
    k_epilogue<<<(NTOT * 16 + 255) / 256, 256>>>(out4);
}

// round 8
// speedup vs baseline: 1.8010x; 1.0715x over previous
#include <cuda_runtime.h>
#include <cuda_fp16.h>
#include <math.h>

// ---------------- problem constants ----------------
#define N_USER   100000
#define N_ITEM   50000
#define NTOT     (N_USER + N_ITEM)     // 150000
#define EMB      64
#define FEAT     384
#define NNZ      2400000
#define N_PROMPT 8
#define N_LAYERS 4
#define EPS_     1e-8f

#define SCAN_BLK 256
#define NB_SCAN  ((NTOT + SCAN_BLK - 1) / SCAN_BLK)   // 586

// ---------------- device scratch (static, no runtime alloc) ----------------
__device__ float  g_ego [NTOT * EMB];     // layer-0 embeddings, fp32
__device__ __half g_hEgo[NTOT * EMB];     // half copy of ego (gather table L0)
__device__ uint4  g_h1  [NTOT * 8];       // x1 (half rows: 8 x uint4 = 64 half)
__device__ uint4  g_h2  [NTOT * 8];       // x2
__device__ uint4  g_h3  [NTOT * 8];       // x3
__device__ float  g_norm[NTOT];           // ||ego|| per row
__device__ int    g_deg   [NTOT];
__device__ int    g_rowptr[NTOT + 1];
__device__ int    g_cursor[NTOT];
__device__ int    g_bsums [1024];
__device__ int    g_boffs [1024];
__device__ int2   g_edges [NNZ];          // {col, float-bits(val)} per edge

// ---------------- 1) user ego = user_fea + prompt-sum (fused) --------------
__global__ void k_user_ego(const float* __restrict__ uf,
                           const float* __restrict__ pe) {
    int i = blockIdx.x * blockDim.x + threadIdx.x;
    if (i >= N_USER * EMB) return;
    int c = i & (EMB - 1);
    float s = 0.f;
    #pragma unroll
    for (int p = 0; p < N_PROMPT; ++p) s += __ldg(&pe[p * EMB + c]);
    float v = uf[i] + s;
    g_ego[i]  = v;
    g_hEgo[i] = __float2half(v);
}

// ---------------- 2) item GEMM + tanh -> ego (fp32 + half copy) ------------
__global__ __launch_bounds__(256) void k_gemm(const float* __restrict__ A,
                                              const float* __restrict__ B,
                                              const float* __restrict__ bias)
{
    __shared__ float As[64][32];
    __shared__ float Bs[32][64];

    const int t     = threadIdx.x;
    const int c     = t & 63;
    const int rq    = t >> 6;
    const int row0  = blockIdx.x * 64;

    float acc[16];
    #pragma unroll
    for (int j = 0; j < 16; ++j) acc[j] = 0.f;

    for (int k0 = 0; k0 < FEAT; k0 += 32) {
        #pragma unroll
        for (int i = 0; i < 8; ++i) {
            int lin = i * 256 + t;
            int r = lin >> 5, k = lin & 31;
            int gr = row0 + r;
            As[r][k] = (gr < N_ITEM) ? A[gr * FEAT + k0 + k] : 0.f;
        }
        #pragma unroll
        for (int i = 0; i < 8; ++i) {
            int lin = i * 256 + t;
            int k = lin >> 6, cc = lin & 63;
            Bs[k][cc] = B[(k0 + k) * EMB + cc];
        }
        __syncthreads();

        float bv[32];
        #pragma unroll
        for (int kk = 0; kk < 32; ++kk) bv[kk] = Bs[kk][c];

        #pragma unroll
        for (int j = 0; j < 16; ++j) {
            const float4* ar = (const float4*)&As[rq * 16 + j][0];
            #pragma unroll
            for (int q = 0; q < 8; ++q) {
                float4 a = ar[q];
                acc[j] += a.x * bv[4*q] + a.y * bv[4*q+1]
                        + a.z * bv[4*q+2] + a.w * bv[4*q+3];
            }
        }
        __syncthreads();
    }

    float bb = bias[c];
    #pragma unroll
    for (int j = 0; j < 16; ++j) {
        int row = row0 + rq * 16 + j;
        if (row < N_ITEM) {
            float v = tanhf(acc[j] + bb);
            g_ego [(N_USER + row) * EMB + c] = v;
            g_hEgo[(N_USER + row) * EMB + c] = __float2half(v);
        }
    }
}

// ---------------- CSR build ----------------
__global__ void k_hist(const int* __restrict__ rows) {
    int e = blockIdx.x * blockDim.x + threadIdx.x;
    if (e < NNZ) atomicAdd(&g_deg[rows[e]], 1);
}
__global__ void k_scan1() {
    __shared__ int sh[SCAN_BLK];
    int t = threadIdx.x;
    int idx = blockIdx.x * SCAN_BLK + t;
    int v = (idx < NTOT) ? g_deg[idx] : 0;
    sh[t] = v;
    __syncthreads();
    for (int off = 1; off < SCAN_BLK; off <<= 1) {
        int add = (t >= off) ? sh[t - off] : 0;
        __syncthreads();
        sh[t] += add;
        __syncthreads();
    }
    if (idx < NTOT) g_rowptr[idx] = sh[t] - v;
    if (t == SCAN_BLK - 1) g_bsums[blockIdx.x] = sh[t];
}
__global__ void k_scan2() {
    __shared__ int sh[1024];
    int t = threadIdx.x;
    int v = (t < NB_SCAN) ? g_bsums[t] : 0;
    sh[t] = v;
    __syncthreads();
    for (int off = 1; off < 1024; off <<= 1) {
        int add = (t >= off) ? sh[t - off] : 0;
        __syncthreads();
        sh[t] += add;
        __syncthreads();
    }
    if (t < NB_SCAN) g_boffs[t] = sh[t] - v;
    if (t == 1023)   g_rowptr[NTOT] = sh[1023];
}
__global__ void k_scan3() {
    int i = blockIdx.x * blockDim.x + threadIdx.x;
    if (i < NTOT) {
        int r = g_rowptr[i] + g_boffs[i >> 8];
        g_rowptr[i] = r;
        g_cursor[i] = r;
    }
}
__global__ void k_scatter(const int* __restrict__ rows,
                          const int* __restrict__ cols,
                          const float* __restrict__ vals) {
    int e = blockIdx.x * blockDim.x + threadIdx.x;
    if (e < NNZ) {
        int p = atomicAdd(&g_cursor[rows[e]], 1);
        g_edges[p] = make_int2(cols[e], __float_as_int(vals[e]));
    }
}

// ---------------- helpers: 16B of halfs <-> 8 floats ----------------
__device__ __forceinline__ void h16_to_f8(uint4 r, float* f) {
    float2 t;
    t = __half22float2(*(__half2*)&r.x); f[0] = t.x; f[1] = t.y;
    t = __half22float2(*(__half2*)&r.y); f[2] = t.x; f[3] = t.y;
    t = __half22float2(*(__half2*)&r.z); f[4] = t.x; f[5] = t.y;
    t = __half22float2(*(__half2*)&r.w); f[6] = t.x; f[7] = t.y;
}
__device__ __forceinline__ uint4 f8_to_h16(const float* f) {
    uint4 r; __half2 h;
    h = __floats2half2_rn(f[0], f[1]); r.x = *(unsigned*)&h;
    h = __floats2half2_rn(f[2], f[3]); r.y = *(unsigned*)&h;
    h = __floats2half2_rn(f[4], f[5]); r.z = *(unsigned*)&h;
    h = __floats2half2_rn(f[6], f[7]); r.w = *(unsigned*)&h;
    return r;
}

// ---------------- fused propagate layer (4 rows per warp) ----------------
// A half row = 64 half = 8 lanes x uint4(16B). Warp quarters (8 lanes)
// process 4 independent rows; one gather instruction serves 4 edges.
// fp32 accumulate; cosine vs fp32 ego; write half xn.
// FIRST: also computes ||ego|| -> g_norm.
// LAST:  instead of xn, writes out = ego + x1 + x2 + x3 + r (fused epilogue).
template<bool FIRST, bool LAST>
__global__ __launch_bounds__(256) void k_prop(const uint4* __restrict__ xh,
                                              uint4* __restrict__ xn,
                                              float4* __restrict__ out)
{
    const unsigned FULL = 0xffffffffu;
    int warp = (blockIdx.x * blockDim.x + threadIdx.x) >> 5;
    int lane = threadIdx.x & 31;
    int hl   = lane & 7;               // lane within quarter
    int row  = warp * 4 + (lane >> 3); // quarter q -> row 4w+q
    if (row >= NTOT) return;

    int beg = g_rowptr[row];
    int end = g_rowptr[row + 1];

    float acc[8];
    #pragma unroll
    for (int k = 0; k < 8; ++k) acc[k] = 0.f;

    int e = beg;
    for (; e + 4 <= end; e += 4) {
        int2 e0 = g_edges[e+0];
        int2 e1 = g_edges[e+1];
        int2 e2 = g_edges[e+2];
        int2 e3 = g_edges[e+3];
        uint4 r0 = xh[e0.x * 8 + hl];
        uint4 r1 = xh[e1.x * 8 + hl];
        uint4 r2 = xh[e2.x * 8 + hl];
        uint4 r3 = xh[e3.x * 8 + hl];
        float x0[8], x1[8], x2[8], x3[8];
        h16_to_f8(r0, x0);
        h16_to_f8(r1, x1);
        h16_to_f8(r2, x2);
        h16_to_f8(r3, x3);
        float v0 = __int_as_float(e0.y);
        float v1 = __int_as_float(e1.y);
        float v2 = __int_as_float(e2.y);
        float v3 = __int_as_float(e3.y);
        #pragma unroll
        for (int k = 0; k < 8; ++k)
            acc[k] += v0*x0[k] + v1*x1[k] + v2*x2[k] + v3*x3[k];
    }
    for (; e < end; ++e) {
        int2  cv = g_edges[e];
        float v  = __int_as_float(cv.y);
        uint4 rr = xh[cv.x * 8 + hl];
        float xv[8];
        h16_to_f8(rr, xv);
        #pragma unroll
        for (int k = 0; k < 8; ++k) acc[k] += v * xv[k];
    }

    // fp32 ego slice: 8 floats = 2 float4 per lane
    const float4* egof = (const float4*)g_ego;
    float4 ea = egof[row * 16 + hl * 2];
    float4 eb = egof[row * 16 + hl * 2 + 1];
    float eg[8] = {ea.x, ea.y, ea.z, ea.w, eb.x, eb.y, eb.z, eb.w};

    float dot = 0.f, nrm = 0.f, egn = 0.f;
    #pragma unroll
    for (int k = 0; k < 8; ++k) {
        dot += acc[k] * eg[k];
        nrm += acc[k] * acc[k];
        if (FIRST) egn += eg[k] * eg[k];
    }
    #pragma unroll
    for (int o = 4; o; o >>= 1) {       // reduce within 8-lane quarter
        dot += __shfl_xor_sync(FULL, dot, o);
        nrm += __shfl_xor_sync(FULL, nrm, o);
        if (FIRST) egn += __shfl_xor_sync(FULL, egn, o);
    }

    float ego_norm;
    if (FIRST) {
        ego_norm = sqrtf(egn);
        if (hl == 0) g_norm[row] = ego_norm;
    } else {
        ego_norm = g_norm[row];
    }
    float w = dot / fmaxf(sqrtf(nrm) * ego_norm, EPS_);

    float r[8];
    #pragma unroll
    for (int k = 0; k < 8; ++k) r[k] = w * acc[k];

    if (LAST) {
        float s1[8], s2[8], s3[8];
        h16_to_f8(g_h1[row * 8 + hl], s1);
        h16_to_f8(g_h2[row * 8 + hl], s2);
        h16_to_f8(g_h3[row * 8 + hl], s3);
        float o0[8];
        #pragma unroll
        for (int k = 0; k < 8; ++k)
            o0[k] = eg[k] + s1[k] + s2[k] + s3[k] + r[k];
        out[row * 16 + hl * 2]     = make_float4(o0[0], o0[1], o0[2], o0[3]);
        out[row * 16 + hl * 2 + 1] = make_float4(o0[4], o0[5], o0[6], o0[7]);
    } else {
        xn[row * 8 + hl] = f8_to_h16(r);
    }
}

// ---------------- launch ----------------
extern "C" void kernel_launch(void* const* d_in, const int* in_sizes, int n_in,
                              void* d_out, int out_size)
{
    const float* user_fea = (const float*)d_in[0];
    const float* item_fea = (const float*)d_in[1];
    const float* prompt   = (const float*)d_in[2];
    const float* mlp_w    = (const float*)d_in[3];
    const float* mlp_b    = (const float*)d_in[4];
    const int*   adj_rows = (const int*)  d_in[5];
    const int*   adj_cols = (const int*)  d_in[6];
    const float* adj_vals = (const float*)d_in[7];
    float* out = (float*)d_out;

    static cudaStream_t s2 = nullptr;
    static cudaEvent_t  evFork = nullptr, evJoin = nullptr;
    if (s2 == nullptr) {
        cudaStreamCreateWithFlags(&s2, cudaStreamNonBlocking);
        cudaEventCreateWithFlags(&evFork, cudaEventDisableTiming);
        cudaEventCreateWithFlags(&evJoin, cudaEventDisableTiming);
    }

    void* degp = nullptr;
    uint4 *hEgo = nullptr, *h1 = nullptr, *h2 = nullptr, *h3 = nullptr;
    cudaGetSymbolAddress(&degp, g_deg);
    cudaGetSymbolAddress((void**)&hEgo, g_hEgo);
    cudaGetSymbolAddress((void**)&h1, g_h1);
    cudaGetSymbolAddress((void**)&h2, g_h2);
    cudaGetSymbolAddress((void**)&h3, g_h3);
    float4* out4 = (float4*)out;

    // ---- fork: CSR build on s2, embeddings on capture (default) stream ----
    cudaEventRecord(evFork, 0);
    cudaStreamWaitEvent(s2, evFork, 0);

    // branch A (default stream): embeddings
    k_user_ego<<<(N_USER * EMB + 255) / 256, 256>>>(user_fea, prompt);
    k_gemm    <<<(N_ITEM + 63) / 64, 256>>>(item_fea, mlp_w, mlp_b);

    // branch B (s2): CSR build
    cudaMemsetAsync(degp, 0, NTOT * sizeof(int), s2);
    k_hist    <<<(NNZ + 255) / 256, 256, 0, s2>>>(adj_rows);
    k_scan1   <<<NB_SCAN, SCAN_BLK, 0, s2>>>();
    k_scan2   <<<1, 1024, 0, s2>>>();
    k_scan3   <<<(NTOT + 255) / 256, 256, 0, s2>>>();
    k_scatter <<<(NNZ + 255) / 256, 256, 0, s2>>>(adj_rows, adj_cols, adj_vals);

    // ---- join ----
    cudaEventRecord(evJoin, s2);
    cudaStreamWaitEvent(0, evJoin, 0);

    // --- 4 propagation layers; last layer fuses the output epilogue ---
    int nwarp   = (NTOT + 3) / 4;                      // 4 rows per warp
    int pblocks = (nwarp * 32 + 255) / 256;
    k_prop<true,  false><<<pblocks, 256>>>(hEgo, h1, nullptr);
    k_prop<false, false><<<pblocks, 256>>>(h1,   h2, nullptr);
    k_prop<false, false><<<pblocks, 256>>>(h2,   h3, nullptr);
    k_prop<false, true ><<<pblocks, 256>>>(h3,   nullptr, out4);
}